// round 12
// baseline (speedup 1.0000x reference)
#include <cuda_runtime.h>
#include <cuda_bf16.h>
#include <math.h>
#include <stdint.h>

#define Bn 4
#define Tn 2048
#define En 1024
#define Hn 16
#define Dh 64
#define Ln 4
#define FFn 4096
#define Vn 32000
#define Rn 8192
#define NEG_HUGE (-1e30f)

__device__ float g_x[Rn * En];
__device__ float g_tmp[Rn * En];
__device__ float g_q[Rn * En];
__device__ float g_k[Rn * En];
__device__ float g_v[Rn * En];
__device__ __nv_bfloat16 g_xh[Rn * En];
__device__ __nv_bfloat16 g_xl[Rn * En];
__device__ __nv_bfloat16 g_ah[Rn * En];
__device__ __nv_bfloat16 g_al[Rn * En];
__device__ __nv_bfloat16 g_hh[(size_t)Rn * FFn];
__device__ __nv_bfloat16 g_hl[(size_t)Rn * FFn];
__device__ __nv_bfloat16 g_wh[(size_t)FFn * En];
__device__ __nv_bfloat16 g_wl[(size_t)FFn * En];
__device__ float g_rl[Rn];

// ---------------- helpers ----------------
__device__ __forceinline__ uint32_t smem_u32(const void* p) {
    uint32_t a;
    asm("{ .reg .u64 t; cvta.to.shared.u64 t, %1; cvt.u32.u64 %0, t; }" : "=r"(a) : "l"(p));
    return a;
}
__device__ __forceinline__ void ldmA(uint32_t* r, uint32_t addr) {
    asm volatile("ldmatrix.sync.aligned.m8n8.x4.shared.b16 {%0,%1,%2,%3}, [%4];"
                 : "=r"(r[0]), "=r"(r[1]), "=r"(r[2]), "=r"(r[3]) : "r"(addr));
}
__device__ __forceinline__ void mma16816(float* c, const uint32_t* a, const uint32_t* b) {
    asm volatile("mma.sync.aligned.m16n8k16.row.col.f32.bf16.bf16.f32 "
                 "{%0,%1,%2,%3}, {%4,%5,%6,%7}, {%8,%9}, {%0,%1,%2,%3};"
                 : "+f"(c[0]), "+f"(c[1]), "+f"(c[2]), "+f"(c[3])
                 : "r"(a[0]), "r"(a[1]), "r"(a[2]), "r"(a[3]), "r"(b[0]), "r"(b[1]));
}
__device__ __forceinline__ void mma_tf32(float* c, const uint32_t* a, const uint32_t* b) {
    asm volatile("mma.sync.aligned.m16n8k8.row.col.f32.tf32.tf32.f32 "
                 "{%0,%1,%2,%3}, {%4,%5,%6,%7}, {%8,%9}, {%0,%1,%2,%3};"
                 : "+f"(c[0]), "+f"(c[1]), "+f"(c[2]), "+f"(c[3])
                 : "r"(a[0]), "r"(a[1]), "r"(a[2]), "r"(a[3]), "r"(b[0]), "r"(b[1]));
}
__device__ __forceinline__ uint32_t to_tf32(float f) {
    uint32_t r;
    asm("cvt.rna.tf32.f32 %0, %1;" : "=r"(r) : "f"(f));
    return r;
}
// raw fp32 bits as tf32 operand (HW truncates low mantissa)
__device__ __forceinline__ uint32_t frg(float f) { return __float_as_uint(f); }
#define CP16(dst, src) asm volatile("cp.async.cg.shared.global [%0], [%1], 16;" \
    :: "r"(dst), "l"(__cvta_generic_to_global(src)) : "memory")
#define CPCOMMIT() asm volatile("cp.async.commit_group;" ::: "memory")
#define CPWAIT1() asm volatile("cp.async.wait_group 1;" ::: "memory")
#define CPWAIT0() asm volatile("cp.async.wait_group 0;" ::: "memory")

__device__ __forceinline__ void split_store4(__nv_bfloat16* ph, __nv_bfloat16* pl,
                                             float a, float b, float c, float d) {
    __nv_bfloat16 h0 = __float2bfloat16(a), h1 = __float2bfloat16(b);
    __nv_bfloat16 h2 = __float2bfloat16(c), h3 = __float2bfloat16(d);
    __nv_bfloat162 A, B;
    A.x = h0; A.y = h1; B.x = h2; B.y = h3;
    *(__nv_bfloat162*)(ph) = A;
    *(__nv_bfloat162*)(ph + 2) = B;
    __nv_bfloat162 C, D;
    C.x = __float2bfloat16(a - __bfloat162float(h0));
    C.y = __float2bfloat16(b - __bfloat162float(h1));
    D.x = __float2bfloat16(c - __bfloat162float(h2));
    D.y = __float2bfloat16(d - __bfloat162float(h3));
    *(__nv_bfloat162*)(pl) = C;
    *(__nv_bfloat162*)(pl + 2) = D;
}
__device__ __forceinline__ void split_store2(__nv_bfloat16* ph, __nv_bfloat16* pl,
                                             float a, float b) {
    __nv_bfloat16 h0 = __float2bfloat16(a), h1 = __float2bfloat16(b);
    __nv_bfloat162 A;
    A.x = h0; A.y = h1;
    *(__nv_bfloat162*)(ph) = A;
    __nv_bfloat162 C;
    C.x = __float2bfloat16(a - __bfloat162float(h0));
    C.y = __float2bfloat16(b - __bfloat162float(h1));
    *(__nv_bfloat162*)(pl) = C;
}

__device__ __forceinline__ bool tok_is64(const void* p) {
    const unsigned long long* q = (const unsigned long long*)p;
    unsigned long long acc = 0ull;
#pragma unroll
    for (int i = 0; i < 8; i++) acc |= (q[i] & 0xFFFFFFFF00000000ull);
    return acc == 0ull;
}
__device__ __forceinline__ int tok_at(const void* p, int i, bool is64) {
    return is64 ? (int)((const long long*)p)[i] : ((const int*)p)[i];
}

// ---------------- embedding ----------------
__global__ void k_embed(const void* __restrict__ idx, const float* __restrict__ tok,
                        const float* __restrict__ pos, float* __restrict__ x) {
    int row = blockIdx.x, t = threadIdx.x;
    bool is64 = tok_is64(idx);
    int token = tok_at(idx, row, is64);
    int tt = row & (Tn - 1);
    float4 a = ((const float4*)(tok + (size_t)token * En))[t];
    float4 p = ((const float4*)(pos + (size_t)tt * En))[t];
    ((float4*)(x + (size_t)row * En))[t] = make_float4(a.x + p.x, a.y + p.y, a.z + p.z, a.w + p.w);
}

// ---------------- QKV (fp32) ----------------
__global__ void __launch_bounds__(256) k_qkv(
    const float* __restrict__ x, const float* __restrict__ Wq,
    const float* __restrict__ Wk, const float* __restrict__ Wv,
    float* __restrict__ q, float* __restrict__ k, float* __restrict__ v) {
    __shared__ float xs[64 * 68];
    __shared__ float wt[64 * 68];
    int r0 = blockIdx.x * 64;
    int b = r0 >> 11, t0 = r0 & 2047;
    int tid = threadIdx.x, tx = tid & 15, ty = tid >> 4;
    for (int h = 0; h < Hn; h++) {
        __syncthreads();
        for (int n = tid; n < 64 * 16; n += 256) {
            int row = n >> 4, c4 = n & 15;
            *(float4*)&xs[row * 68 + c4 * 4] =
                *(const float4*)(x + (size_t)(r0 + row) * En + h * 64 + c4 * 4);
        }
        for (int mm = 0; mm < 3; mm++) {
            const float* Wm = (mm == 0) ? Wq : (mm == 1) ? Wk : Wv;
            float* Om = (mm == 0) ? q : (mm == 1) ? k : v;
            __syncthreads();
            for (int n = tid; n < 64 * 16; n += 256) {
                int e = n >> 4, c4 = n & 15;
                float4 val = *(const float4*)(Wm + e * 64 + c4 * 4);
                wt[(c4 * 4 + 0) * 68 + e] = val.x;
                wt[(c4 * 4 + 1) * 68 + e] = val.y;
                wt[(c4 * 4 + 2) * 68 + e] = val.z;
                wt[(c4 * 4 + 3) * 68 + e] = val.w;
            }
            __syncthreads();
            float acc[4][4] = {};
            for (int d = 0; d < 64; d++) {
                float a0 = xs[(ty * 4 + 0) * 68 + d];
                float a1 = xs[(ty * 4 + 1) * 68 + d];
                float a2 = xs[(ty * 4 + 2) * 68 + d];
                float a3 = xs[(ty * 4 + 3) * 68 + d];
                float4 bv = *(const float4*)&wt[d * 68 + tx * 4];
                acc[0][0] += a0 * bv.x; acc[0][1] += a0 * bv.y; acc[0][2] += a0 * bv.z; acc[0][3] += a0 * bv.w;
                acc[1][0] += a1 * bv.x; acc[1][1] += a1 * bv.y; acc[1][2] += a1 * bv.z; acc[1][3] += a1 * bv.w;
                acc[2][0] += a2 * bv.x; acc[2][1] += a2 * bv.y; acc[2][2] += a2 * bv.z; acc[2][3] += a2 * bv.w;
                acc[3][0] += a3 * bv.x; acc[3][1] += a3 * bv.y; acc[3][2] += a3 * bv.z; acc[3][3] += a3 * bv.w;
            }
#pragma unroll
            for (int ri = 0; ri < 4; ri++) {
                size_t off = ((size_t)((b * Hn + h) * Tn + t0 + ty * 4 + ri)) * Dh + tx * 4;
                *(float4*)(Om + off) = make_float4(acc[ri][0], acc[ri][1], acc[ri][2], acc[ri][3]);
            }
        }
    }
}

// ---------------- tensor-core flash attention: 128 q-rows/block, 8 warps,
//                  raw-bit tf32 operands, hoisted Q fragments ----------
#define ASTR 68
#define KOFF (128 * ASTR * 4)
#define VOFF (KOFF + 2 * 17408)
#define POFF (VOFF + 2 * 17408)
#define ATT_SMEM (POFF + 8 * 16 * ASTR * 4)
__global__ void __launch_bounds__(256) k_attn_tc(
    const float* __restrict__ q, const float* __restrict__ k,
    const float* __restrict__ v, __nv_bfloat16* __restrict__ oh,
    __nv_bfloat16* __restrict__ ol) {
    extern __shared__ float sm[];
    uint32_t sb = smem_u32(sm);
    int qt = blockIdx.x, hh = blockIdx.y, b = blockIdx.z;
    int tid = threadIdx.x, w = tid >> 5, l = tid & 31;
    int lg = l >> 2, lt = l & 3;

    const float* qb = q + ((size_t)(b * Hn + hh) * Tn + qt * 128) * Dh;
    const float* kb = k + ((size_t)(b * Hn + hh) * Tn) * Dh;
    const float* vb = v + ((size_t)(b * Hn + hh) * Tn) * Dh;

    {
        int r = tid >> 1, c = (tid & 1) * 32;
#pragma unroll
        for (int i = 0; i < 8; i++)
            *(float4*)&sm[r * ASTR + c + i * 4] = *(const float4*)(qb + r * 64 + c + i * 4);
    }
#define FILLKV(st, kt) do {                                                    \
    int _r = tid >> 2, _c = (tid & 3) * 16;                                    \
    const float* _kp = kb + ((size_t)(kt) * 64 + _r) * 64 + _c;                \
    const float* _vp = vb + ((size_t)(kt) * 64 + _r) * 64 + _c;                \
    uint32_t _dk = sb + KOFF + (st) * 17408 + (uint32_t)(_r * ASTR + _c) * 4;  \
    uint32_t _dv = sb + VOFF + (st) * 17408 + (uint32_t)(_r * ASTR + _c) * 4;  \
    _Pragma("unroll")                                                          \
    for (int _i = 0; _i < 4; _i++) {                                           \
        CP16(_dk + _i * 16, _kp + _i * 4);                                     \
        CP16(_dv + _i * 16, _vp + _i * 4);                                     \
    }                                                                          \
} while (0)

    FILLKV(0, 0);
    CPCOMMIT();
    __syncthreads();  // Q tile visible

    // hoist Q fragments (raw fp32 bits; Q region never overwritten)
    uint32_t qf[8][4];
#pragma unroll
    for (int ks = 0; ks < 8; ks++) {
        const float* qp = &sm[(w * 16 + lg) * ASTR + ks * 8 + lt];
        qf[ks][0] = frg(qp[0]);
        qf[ks][1] = frg(qp[8 * ASTR]);
        qf[ks][2] = frg(qp[4]);
        qf[ks][3] = frg(qp[8 * ASTR + 4]);
    }

    float m0 = NEG_HUGE, m1 = NEG_HUGE, l0 = 0.f, l1 = 0.f;
    float oacc[8][4];
#pragma unroll
    for (int nt = 0; nt < 8; nt++)
#pragma unroll
        for (int c = 0; c < 4; c++) oacc[nt][c] = 0.f;

    float* pw = sm + POFF / 4 + w * 16 * ASTR;
    int gr0 = qt * 128 + w * 16 + lg;
    int gr1 = gr0 + 8;

    int nkt = 2 * qt + 1;
    for (int kt = 0; kt <= nkt; kt++) {
        __syncthreads();
        if (kt + 1 <= nkt) {
            FILLKV((kt + 1) & 1, kt + 1);
            CPCOMMIT();
            CPWAIT1();
        } else {
            CPWAIT0();
        }
        __syncthreads();
        const float* Ks = sm + KOFF / 4 + (kt & 1) * 4352;
        const float* Vs = sm + VOFF / 4 + (kt & 1) * 4352;

        float sacc[8][4];
#pragma unroll
        for (int nt = 0; nt < 8; nt++)
#pragma unroll
            for (int c = 0; c < 4; c++) sacc[nt][c] = 0.f;
#pragma unroll
        for (int ks = 0; ks < 8; ks++) {
#pragma unroll
            for (int nt = 0; nt < 8; nt++) {
                uint32_t bf[2];
                const float* kp = &Ks[(nt * 8 + lg) * ASTR + ks * 8 + lt];
                bf[0] = frg(kp[0]);
                bf[1] = frg(kp[4]);
                mma_tf32(sacc[nt], qf[ks], bf);
            }
        }
        float mx0 = NEG_HUGE, mx1 = NEG_HUGE;
#pragma unroll
        for (int nt = 0; nt < 8; nt++) {
#pragma unroll
            for (int j = 0; j < 2; j++) {
                int gc = kt * 64 + nt * 8 + lt * 2 + j;
                float s0 = sacc[nt][j] * 0.125f;
                float s1 = sacc[nt][2 + j] * 0.125f;
                if (gc > gr0) s0 = NEG_HUGE;
                if (gc > gr1) s1 = NEG_HUGE;
                sacc[nt][j] = s0;
                sacc[nt][2 + j] = s1;
                mx0 = fmaxf(mx0, s0);
                mx1 = fmaxf(mx1, s1);
            }
        }
        mx0 = fmaxf(mx0, __shfl_xor_sync(0xffffffffu, mx0, 1));
        mx0 = fmaxf(mx0, __shfl_xor_sync(0xffffffffu, mx0, 2));
        mx1 = fmaxf(mx1, __shfl_xor_sync(0xffffffffu, mx1, 1));
        mx1 = fmaxf(mx1, __shfl_xor_sync(0xffffffffu, mx1, 2));
        float mn0 = fmaxf(m0, mx0), mn1 = fmaxf(m1, mx1);
        float cr0 = __expf(m0 - mn0), cr1 = __expf(m1 - mn1);
        m0 = mn0; m1 = mn1;
        float ps0 = 0.f, ps1 = 0.f;
#pragma unroll
        for (int nt = 0; nt < 8; nt++) {
#pragma unroll
            for (int j = 0; j < 2; j++) {
                float p0 = __expf(sacc[nt][j] - mn0);
                float p1 = __expf(sacc[nt][2 + j] - mn1);
                sacc[nt][j] = p0;
                sacc[nt][2 + j] = p1;
                ps0 += p0;
                ps1 += p1;
            }
        }
        ps0 += __shfl_xor_sync(0xffffffffu, ps0, 1);
        ps0 += __shfl_xor_sync(0xffffffffu, ps0, 2);
        ps1 += __shfl_xor_sync(0xffffffffu, ps1, 1);
        ps1 += __shfl_xor_sync(0xffffffffu, ps1, 2);
        l0 = l0 * cr0 + ps0;
        l1 = l1 * cr1 + ps1;
#pragma unroll
        for (int nt = 0; nt < 8; nt++) {
            oacc[nt][0] *= cr0; oacc[nt][1] *= cr0;
            oacc[nt][2] *= cr1; oacc[nt][3] *= cr1;
        }
#pragma unroll
        for (int nt = 0; nt < 8; nt++) {
            *(float2*)&pw[lg * ASTR + nt * 8 + lt * 2] = make_float2(sacc[nt][0], sacc[nt][1]);
            *(float2*)&pw[(lg + 8) * ASTR + nt * 8 + lt * 2] = make_float2(sacc[nt][2], sacc[nt][3]);
        }
        __syncwarp();
#pragma unroll
        for (int ks = 0; ks < 8; ks++) {
            uint32_t af[4];
            const float* pp = &pw[lg * ASTR + ks * 8 + lt];
            af[0] = frg(pp[0]);
            af[1] = frg(pp[8 * ASTR]);
            af[2] = frg(pp[4]);
            af[3] = frg(pp[8 * ASTR + 4]);
#pragma unroll
            for (int nt = 0; nt < 8; nt++) {
                uint32_t bf[2];
                const float* vp = &Vs[(ks * 8 + lt) * ASTR + nt * 8 + lg];
                bf[0] = frg(vp[0]);
                bf[1] = frg(vp[4 * ASTR]);
                mma_tf32(oacc[nt], af, bf);
            }
        }
        __syncwarp();
    }
    float inv0 = 1.f / l0, inv1 = 1.f / l1;
    size_t base0 = ((size_t)(b * Tn) + gr0) * En + hh * 64;
    size_t base1 = base0 + (size_t)8 * En;
#pragma unroll
    for (int nt = 0; nt < 8; nt++) {
        int cc = nt * 8 + lt * 2;
        split_store2(oh + base0 + cc, ol + base0 + cc, oacc[nt][0] * inv0, oacc[nt][1] * inv0);
        split_store2(oh + base1 + cc, ol + base1 + cc, oacc[nt][2] * inv1, oacc[nt][3] * inv1);
    }
}

// ---------------- HMMA bf16 3-split GEMM: 256x128 tile, 512 threads ----------------
#define SSTR 40
#define A_MATB 20480      /* 256*40*2 */
#define B_MATB 10240      /* 128*40*2 */
#define STAGEB (2 * A_MATB + 2 * B_MATB)  /* 61440 */
#define GEMM_SMEM (2 * STAGEB)            /* 122880 */
#define GFILL(bsel, kc) do {                                                  \
    uint32_t _b = sb + (bsel) * STAGEB;                                       \
    size_t _o = (size_t)(kc) * 32;                                            \
    CP16(_b + sAo, pXh + _o); CP16(_b + sAo + 16, pXh + _o + 8);              \
    CP16(_b + A_MATB + sAo, pXl + _o); CP16(_b + A_MATB + sAo + 16, pXl + _o + 8); \
    CP16(_b + 2 * A_MATB + sBo, pWh + _o);                                    \
    CP16(_b + 2 * A_MATB + B_MATB + sBo, pWl + _o);                           \
} while (0)

template <int ACT, int SPLIT>
__global__ void __launch_bounds__(512, 1) k_gemm_mma(
    const __nv_bfloat16* __restrict__ Xh, const __nv_bfloat16* __restrict__ Xl,
    const __nv_bfloat16* __restrict__ Wh, const __nv_bfloat16* __restrict__ Wl,
    const float* __restrict__ bias, float* __restrict__ Yf,
    __nv_bfloat16* __restrict__ Yh, __nv_bfloat16* __restrict__ Yl,
    int M, int N, int K) {
    extern __shared__ char dsm[];
    uint32_t sb = smem_u32(dsm);
    int tid = threadIdx.x, wid = tid >> 5, lane = tid & 31;
    int bm = blockIdx.x * 256, bn = blockIdx.y * 128;
    int wm = (wid >> 2) * 64, wn = (wid & 3) * 32;
    float acc[4][4][4];
#pragma unroll
    for (int a = 0; a < 4; a++)
#pragma unroll
        for (int b = 0; b < 4; b++)
#pragma unroll
            for (int c = 0; c < 4; c++) acc[a][b][c] = 0.f;

    int ra = tid >> 1, ca = (tid & 1) * 16;
    int rb = tid >> 2, cb = (tid & 3) * 8;
    uint32_t sAo = (uint32_t)(ra * SSTR + ca) * 2;
    uint32_t sBo = (uint32_t)(rb * SSTR + cb) * 2;
    const __nv_bfloat16* pXh = Xh + (size_t)(bm + ra) * K + ca;
    const __nv_bfloat16* pXl = Xl + (size_t)(bm + ra) * K + ca;
    const __nv_bfloat16* pWh = Wh + (size_t)(bn + rb) * K + cb;
    const __nv_bfloat16* pWl = Wl + (size_t)(bn + rb) * K + cb;

    uint32_t a_row = (lane & 15), a_half = (lane >> 4);
    uint32_t b_nrow = (lane & 7) + ((lane >> 4) & 1) * 8;
    uint32_t b_half = (lane >> 3) & 1;

    int NK = K >> 5;
    GFILL(0, 0);
    CPCOMMIT();
    for (int kc = 0; kc < NK; kc++) {
        CPWAIT0();
        __syncthreads();
        if (kc + 1 < NK) {
            GFILL((kc + 1) & 1, kc + 1);
            CPCOMMIT();
        }
        uint32_t bb = sb + (kc & 1) * STAGEB;
        uint32_t aAh = bb, aAl = bb + A_MATB;
        uint32_t aBh = bb + 2 * A_MATB, aBl = bb + 2 * A_MATB + B_MATB;
#pragma unroll
        for (int ks = 0; ks < 2; ks++) {
            uint32_t ah[4][4], al[4][4];
#pragma unroll
            for (int mt = 0; mt < 4; mt++) {
                uint32_t ro = (uint32_t)(wm + mt * 16 + a_row) * (SSTR * 2) + a_half * 16 + ks * 32;
                ldmA(ah[mt], aAh + ro);
                ldmA(al[mt], aAl + ro);
            }
#pragma unroll
            for (int ntp = 0; ntp < 2; ntp++) {
                uint32_t ro = (uint32_t)(wn + ntp * 16 + b_nrow) * (SSTR * 2) + b_half * 16 + ks * 32;
                uint32_t bh4[4], bl4[4];
                ldmA(bh4, aBh + ro);
                ldmA(bl4, aBl + ro);
#pragma unroll
                for (int mt = 0; mt < 4; mt++) {
                    mma16816(acc[mt][2 * ntp], ah[mt], bh4);
                    mma16816(acc[mt][2 * ntp], ah[mt], bl4);
                    mma16816(acc[mt][2 * ntp], al[mt], bh4);
                    mma16816(acc[mt][2 * ntp + 1], ah[mt], bh4 + 2);
                    mma16816(acc[mt][2 * ntp + 1], ah[mt], bl4 + 2);
                    mma16816(acc[mt][2 * ntp + 1], al[mt], bh4 + 2);
                }
            }
        }
    }
#pragma unroll
    for (int mt = 0; mt < 4; mt++) {
#pragma unroll
        for (int nt = 0; nt < 4; nt++) {
            int rr = bm + wm + mt * 16 + (lane >> 2);
            int cc = bn + wn + nt * 8 + (lane & 3) * 2;
            float b0 = __ldg(bias + cc), b1 = __ldg(bias + cc + 1);
            float v0 = acc[mt][nt][0] + b0, v1 = acc[mt][nt][1] + b1;
            float v2 = acc[mt][nt][2] + b0, v3 = acc[mt][nt][3] + b1;
            if (ACT) {
                v0 = 0.5f * v0 * (1.0f + erff(v0 * 0.70710678f));
                v1 = 0.5f * v1 * (1.0f + erff(v1 * 0.70710678f));
                v2 = 0.5f * v2 * (1.0f + erff(v2 * 0.70710678f));
                v3 = 0.5f * v3 * (1.0f + erff(v3 * 0.70710678f));
            }
            if (SPLIT == 0) {
                *(float2*)(Yf + (size_t)rr * N + cc) = make_float2(v0, v1);
                *(float2*)(Yf + (size_t)(rr + 8) * N + cc) = make_float2(v2, v3);
            } else {
                split_store2(Yh + (size_t)rr * N + cc, Yl + (size_t)rr * N + cc, v0, v1);
                split_store2(Yh + (size_t)(rr + 8) * N + cc, Yl + (size_t)(rr + 8) * N + cc, v2, v3);
            }
        }
    }
}

// ---------------- tf32 single-pass GEMM (LM head), single-sync pipeline -------------
#define FSTR 36
#define FMATB (128 * FSTR * 4)
#define FBUFB (2 * FMATB)
__global__ void __launch_bounds__(256, 2) k_gemm32(
    const float* __restrict__ X, const float* __restrict__ W,
    const float* __restrict__ bias, float* __restrict__ Y, int M, int N, int K) {
    extern __shared__ char dsm[];
    uint32_t sb = smem_u32(dsm);
    int tid = threadIdx.x, wid = tid >> 5, lane = tid & 31;
    int bm = blockIdx.x * 128, bn = blockIdx.y * 128;
    int wm = (wid >> 2) * 64, wn = (wid & 3) * 32;
    float acc[4][4][4];
#pragma unroll
    for (int a = 0; a < 4; a++)
#pragma unroll
        for (int b = 0; b < 4; b++)
#pragma unroll
            for (int c = 0; c < 4; c++) acc[a][b][c] = 0.f;
    int NK = K >> 5;
#define F32FILL(bsel, kc) do {                                                \
    uint32_t _b = sb + (bsel) * FBUFB;                                        \
    int _k0 = (kc) * 32;                                                      \
    _Pragma("unroll")                                                         \
    for (int it = 0; it < 4; it++) {                                          \
        int _i = tid + it * 256;                                              \
        int _r = _i >> 3, _c = (_i & 7) * 4;                                  \
        CP16(_b + (uint32_t)(_r * FSTR + _c) * 4, X + (size_t)(bm + _r) * K + _k0 + _c); \
        CP16(_b + FMATB + (uint32_t)(_r * FSTR + _c) * 4, W + (size_t)(bn + _r) * K + _k0 + _c); \
    }                                                                         \
} while (0)
    F32FILL(0, 0);
    CPCOMMIT();
    for (int kc = 0; kc < NK; kc++) {
        CPWAIT0();
        __syncthreads();
        if (kc + 1 < NK) {
            F32FILL((kc + 1) & 1, kc + 1);
            CPCOMMIT();
        }
        const float* fA = (const float*)(dsm + (kc & 1) * FBUFB);
        const float* fB = (const float*)(dsm + (kc & 1) * FBUFB + FMATB);
#pragma unroll
        for (int ks = 0; ks < 4; ks++) {
            uint32_t a[4][4], b[4][2];
#pragma unroll
            for (int mt = 0; mt < 4; mt++) {
                const float* pa = fA + (wm + mt * 16 + (lane >> 2)) * FSTR + ks * 8 + (lane & 3);
                a[mt][0] = to_tf32(pa[0]);
                a[mt][1] = to_tf32(pa[8 * FSTR]);
                a[mt][2] = to_tf32(pa[4]);
                a[mt][3] = to_tf32(pa[8 * FSTR + 4]);
            }
#pragma unroll
            for (int nt = 0; nt < 4; nt++) {
                const float* pb = fB + (wn + nt * 8 + (lane >> 2)) * FSTR + ks * 8 + (lane & 3);
                b[nt][0] = to_tf32(pb[0]);
                b[nt][1] = to_tf32(pb[4]);
            }
#pragma unroll
            for (int mt = 0; mt < 4; mt++)
#pragma unroll
                for (int nt = 0; nt < 4; nt++) mma_tf32(acc[mt][nt], a[mt], b[nt]);
        }
    }
#pragma unroll
    for (int mt = 0; mt < 4; mt++) {
#pragma unroll
        for (int nt = 0; nt < 4; nt++) {
            int rr = bm + wm + mt * 16 + (lane >> 2);
            int cc = bn + wn + nt * 8 + (lane & 3) * 2;
            float b0 = __ldg(bias + cc), b1 = __ldg(bias + cc + 1);
            *(float2*)(Y + (size_t)rr * N + cc) = make_float2(acc[mt][nt][0] + b0, acc[mt][nt][1] + b1);
            *(float2*)(Y + (size_t)(rr + 8) * N + cc) = make_float2(acc[mt][nt][2] + b0, acc[mt][nt][3] + b1);
        }
    }
}

// ---------------- residual add + layernorm ----------------
__global__ void k_addln(const float* __restrict__ a, const float* __restrict__ res,
                        const float* __restrict__ g, const float* __restrict__ bta,
                        float* __restrict__ out, __nv_bfloat16* __restrict__ oh,
                        __nv_bfloat16* __restrict__ ol, int hasres) {
    int row = blockIdx.x, t = threadIdx.x;
    float4 vv = ((const float4*)(a + (size_t)row * En))[t];
    if (hasres) {
        float4 r = ((const float4*)(res + (size_t)row * En))[t];
        vv.x += r.x; vv.y += r.y; vv.z += r.z; vv.w += r.w;
    }
    float s1 = vv.x + vv.y + vv.z + vv.w;
    float s2 = vv.x * vv.x + vv.y * vv.y + vv.z * vv.z + vv.w * vv.w;
#pragma unroll
    for (int off = 16; off; off >>= 1) {
        s1 += __shfl_down_sync(0xffffffffu, s1, off);
        s2 += __shfl_down_sync(0xffffffffu, s2, off);
    }
    __shared__ float r1[8], r2[8];
    __shared__ float bmean, brs;
    int w = t >> 5, lane = t & 31;
    if (lane == 0) { r1[w] = s1; r2[w] = s2; }
    __syncthreads();
    if (t == 0) {
        float a1 = 0.f, a2 = 0.f;
#pragma unroll
        for (int i2 = 0; i2 < 8; i2++) { a1 += r1[i2]; a2 += r2[i2]; }
        float mean = a1 * (1.0f / En);
        bmean = mean;
        brs = rsqrtf(a2 * (1.0f / En) - mean * mean + 1e-5f);
    }
    __syncthreads();
    float mean = bmean, rs = brs;
    float4 gg = ((const float4*)g)[t];
    float4 bb = ((const float4*)bta)[t];
    float4 o;
    o.x = (vv.x - mean) * rs * gg.x + bb.x;
    o.y = (vv.y - mean) * rs * gg.y + bb.y;
    o.z = (vv.z - mean) * rs * gg.z + bb.z;
    o.w = (vv.w - mean) * rs * gg.w + bb.w;
    ((float4*)(out + (size_t)row * En))[t] = o;
    split_store4(oh + (size_t)row * En + 4 * t, ol + (size_t)row * En + 4 * t, o.x, o.y, o.z, o.w);
}

// ---------------- weight splitter ----------------
__global__ void k_split(const float* __restrict__ s, __nv_bfloat16* __restrict__ h,
                        __nv_bfloat16* __restrict__ l, int n4) {
    int i = blockIdx.x * 256 + threadIdx.x;
    if (i >= n4) return;
    float4 v = ((const float4*)s)[i];
    split_store4(h + 4 * i, l + 4 * i, v.x, v.y, v.z, v.w);
}

// ---------------- loss ----------------
__device__ __forceinline__ void lse_acc(float& m, float& s, float xv) {
    if (xv <= m) s += __expf(xv - m);
    else { s = s * __expf(m - xv) + 1.f; m = xv; }
}
__device__ __forceinline__ void lse_merge(float& m, float& s, float mo, float so) {
    float M = fmaxf(m, mo);
    s = s * __expf(m - M) + so * __expf(mo - M);
    m = M;
}
__global__ void k_rowloss(const float* __restrict__ logits, const void* __restrict__ tgt,
                          float* __restrict__ rl) {
    int row = blockIdx.x, t = threadIdx.x;
    const float* lp = logits + (size_t)row * Vn;
    float m = NEG_HUGE, s = 0.f;
    for (int c = 4 * t; c < Vn; c += 1024) {
        float4 vv = *(const float4*)(lp + c);
        lse_acc(m, s, vv.x); lse_acc(m, s, vv.y); lse_acc(m, s, vv.z); lse_acc(m, s, vv.w);
    }
#pragma unroll
    for (int off = 16; off; off >>= 1) {
        float mo = __shfl_down_sync(0xffffffffu, m, off);
        float so = __shfl_down_sync(0xffffffffu, s, off);
        lse_merge(m, s, mo, so);
    }
    __shared__ float rm[8], rs2[8];
    int w = t >> 5, lane = t & 31;
    if (lane == 0) { rm[w] = m; rs2[w] = s; }
    __syncthreads();
    if (t == 0) {
#pragma unroll
        for (int i2 = 1; i2 < 8; i2++) lse_merge(rm[0], rs2[0], rm[i2], rs2[i2]);
        bool is64 = tok_is64(tgt);
        int tv = tok_at(tgt, row, is64);
        rl[row] = (rm[0] + logf(rs2[0])) - lp[tv];
    }
}
__global__ void k_lossfinal(const float* __restrict__ rl, float* __restrict__ dst) {
    int t = threadIdx.x;
    float s = 0.f;
    for (int i = t; i < Rn; i += 256) s += rl[i];
#pragma unroll
    for (int off = 16; off; off >>= 1) s += __shfl_down_sync(0xffffffffu, s, off);
    __shared__ float red[8];
    int w = t >> 5, lane = t & 31;
    if (lane == 0) red[w] = s;
    __syncthreads();
    if (t == 0) {
        float a = 0.f;
#pragma unroll
        for (int i2 = 0; i2 < 8; i2++) a += red[i2];
        dst[0] = a * (1.0f / Rn);
    }
}

extern "C" void kernel_launch(void* const* d_in, const int* in_sizes, int n_in,
                              void* d_out, int out_size) {
    const void* idx = d_in[0];
    const void* tgt = d_in[1];
    const float* tok = (const float*)d_in[2];
    const float* pos = (const float*)d_in[3];
    const float* Wq = (const float*)d_in[4];
    const float* Wk = (const float*)d_in[5];
    const float* Wv = (const float*)d_in[6];
    const float* Wo = (const float*)d_in[7];
    const float* bo = (const float*)d_in[8];
    const float* ln1g = (const float*)d_in[9];
    const float* ln1b = (const float*)d_in[10];
    const float* W1 = (const float*)d_in[11];
    const float* b1 = (const float*)d_in[12];
    const float* W2 = (const float*)d_in[13];
    const float* b2 = (const float*)d_in[14];
    const float* ln2g = (const float*)d_in[15];
    const float* ln2b = (const float*)d_in[16];
    const float* lnfg = (const float*)d_in[17];
    const float* lnfb = (const float*)d_in[18];
    const float* lmw = (const float*)d_in[19];
    const float* lmb = (const float*)d_in[20];
    float* out = (float*)d_out;

    float *x, *tmp, *q, *k, *v, *rl;
    __nv_bfloat16 *xh, *xl, *ah, *al, *hh, *hl, *wh, *wl;
    cudaGetSymbolAddress((void**)&x, g_x);
    cudaGetSymbolAddress((void**)&tmp, g_tmp);
    cudaGetSymbolAddress((void**)&q, g_q);
    cudaGetSymbolAddress((void**)&k, g_k);
    cudaGetSymbolAddress((void**)&v, g_v);
    cudaGetSymbolAddress((void**)&rl, g_rl);
    cudaGetSymbolAddress((void**)&xh, g_xh);
    cudaGetSymbolAddress((void**)&xl, g_xl);
    cudaGetSymbolAddress((void**)&ah, g_ah);
    cudaGetSymbolAddress((void**)&al, g_al);
    cudaGetSymbolAddress((void**)&hh, g_hh);
    cudaGetSymbolAddress((void**)&hl, g_hl);
    cudaGetSymbolAddress((void**)&wh, g_wh);
    cudaGetSymbolAddress((void**)&wl, g_wl);

    cudaFuncSetAttribute(k_attn_tc, cudaFuncAttributeMaxDynamicSharedMemorySize, ATT_SMEM);
    cudaFuncSetAttribute(k_gemm_mma<0, 0>, cudaFuncAttributeMaxDynamicSharedMemorySize, GEMM_SMEM);
    cudaFuncSetAttribute(k_gemm_mma<1, 1>, cudaFuncAttributeMaxDynamicSharedMemorySize, GEMM_SMEM);
    const int f32_smem = 2 * FBUFB;
    cudaFuncSetAttribute(k_gemm32, cudaFuncAttributeMaxDynamicSharedMemorySize, f32_smem);

    k_embed<<<Rn, 256>>>(idx, tok, pos, x);
    for (int l = 0; l < Ln; l++) {
        k_qkv<<<Rn / 64, 256>>>(x, Wq + (size_t)l * Dh * Dh, Wk + (size_t)l * Dh * Dh,
                                Wv + (size_t)l * Dh * Dh, q, k, v);
        k_split<<<(En * En / 4 + 255) / 256, 256>>>(Wo + (size_t)l * En * En, wh, wl, En * En / 4);
        k_attn_tc<<<dim3(Tn / 128, Hn, Bn), 256, ATT_SMEM>>>(q, k, v, ah, al);
        k_gemm_mma<0, 0><<<dim3(Rn / 256, En / 128), 512, GEMM_SMEM>>>(
            ah, al, wh, wl, bo + (size_t)l * En, tmp, nullptr, nullptr, Rn, En, En);
        k_addln<<<Rn, 256>>>(tmp, x, ln1g + (size_t)l * En, ln1b + (size_t)l * En, x, xh, xl, 1);
        k_split<<<((size_t)FFn * En / 4 + 255) / 256, 256>>>(W1 + (size_t)l * FFn * En, wh, wl, FFn * En / 4);
        k_gemm_mma<1, 1><<<dim3(Rn / 256, FFn / 128), 512, GEMM_SMEM>>>(
            xh, xl, wh, wl, b1 + (size_t)l * FFn, nullptr, hh, hl, Rn, FFn, En);
        k_split<<<((size_t)En * FFn / 4 + 255) / 256, 256>>>(W2 + (size_t)l * En * FFn, wh, wl, En * FFn / 4);
        k_gemm_mma<0, 0><<<dim3(Rn / 256, En / 128), 512, GEMM_SMEM>>>(
            hh, hl, wh, wl, b2 + (size_t)l * En, tmp, nullptr, nullptr, Rn, En, FFn);
        k_addln<<<Rn, 256>>>(tmp, x, ln2g + (size_t)l * En, ln2b + (size_t)l * En, x, xh, xl, 1);
    }
    k_addln<<<Rn, 256>>>(x, x, lnfg, lnfb, x, xh, xl, 0);
    k_gemm32<<<dim3(Rn / 128, Vn / 128), 256, f32_smem>>>(x, lmw, lmb, out, Rn, Vn, En);
    if ((long long)out_size > (long long)Rn * Vn) {
        k_rowloss<<<Rn, 256>>>(out, tgt, rl);
        k_lossfinal<<<1, 256>>>(rl, out + (size_t)Rn * Vn);
    }
}

// round 14
// speedup vs baseline: 1.0858x; 1.0858x over previous
#include <cuda_runtime.h>
#include <cuda_bf16.h>
#include <math.h>
#include <stdint.h>

#define Bn 4
#define Tn 2048
#define En 1024
#define Hn 16
#define Dh 64
#define Ln 4
#define FFn 4096
#define Vn 32000
#define Rn 8192
#define NEG_HUGE (-1e30f)

__device__ float g_x[Rn * En];
__device__ float g_tmp[Rn * En];
__device__ float g_q[Rn * En];
__device__ float g_k[Rn * En];
__device__ float g_v[Rn * En];
__device__ float g_att[Rn * En];
__device__ float g_h[(size_t)Rn * FFn];
__device__ float g_rl[Rn];

// ---------------- helpers ----------------
__device__ __forceinline__ uint32_t smem_u32(const void* p) {
    uint32_t a;
    asm("{ .reg .u64 t; cvta.to.shared.u64 t, %1; cvt.u32.u64 %0, t; }" : "=r"(a) : "l"(p));
    return a;
}
__device__ __forceinline__ void mma_tf32(float* c, const uint32_t* a, const uint32_t* b) {
    asm volatile("mma.sync.aligned.m16n8k8.row.col.f32.tf32.tf32.f32 "
                 "{%0,%1,%2,%3}, {%4,%5,%6,%7}, {%8,%9}, {%0,%1,%2,%3};"
                 : "+f"(c[0]), "+f"(c[1]), "+f"(c[2]), "+f"(c[3])
                 : "r"(a[0]), "r"(a[1]), "r"(a[2]), "r"(a[3]), "r"(b[0]), "r"(b[1]));
}
__device__ __forceinline__ uint32_t to_tf32(float f) {
    uint32_t r;
    asm("cvt.rna.tf32.f32 %0, %1;" : "=r"(r) : "f"(f));
    return r;
}
__device__ __forceinline__ uint32_t frg(float f) { return __float_as_uint(f); }
#define CP16(dst, src) asm volatile("cp.async.cg.shared.global [%0], [%1], 16;" \
    :: "r"(dst), "l"(__cvta_generic_to_global(src)) : "memory")
#define CPCOMMIT() asm volatile("cp.async.commit_group;" ::: "memory")
#define CPWAIT1() asm volatile("cp.async.wait_group 1;" ::: "memory")
#define CPWAIT0() asm volatile("cp.async.wait_group 0;" ::: "memory")

__device__ __forceinline__ bool tok_is64(const void* p) {
    const unsigned long long* q = (const unsigned long long*)p;
    unsigned long long acc = 0ull;
#pragma unroll
    for (int i = 0; i < 8; i++) acc |= (q[i] & 0xFFFFFFFF00000000ull);
    return acc == 0ull;
}
__device__ __forceinline__ int tok_at(const void* p, int i, bool is64) {
    return is64 ? (int)((const long long*)p)[i] : ((const int*)p)[i];
}

// ---------------- embedding ----------------
__global__ void k_embed(const void* __restrict__ idx, const float* __restrict__ tok,
                        const float* __restrict__ pos, float* __restrict__ x) {
    int row = blockIdx.x, t = threadIdx.x;
    bool is64 = tok_is64(idx);
    int token = tok_at(idx, row, is64);
    int tt = row & (Tn - 1);
    float4 a = ((const float4*)(tok + (size_t)token * En))[t];
    float4 p = ((const float4*)(pos + (size_t)tt * En))[t];
    ((float4*)(x + (size_t)row * En))[t] = make_float4(a.x + p.x, a.y + p.y, a.z + p.z, a.w + p.w);
}

// ---------------- QKV (fp32) ----------------
__global__ void __launch_bounds__(256) k_qkv(
    const float* __restrict__ x, const float* __restrict__ Wq,
    const float* __restrict__ Wk, const float* __restrict__ Wv,
    float* __restrict__ q, float* __restrict__ k, float* __restrict__ v) {
    __shared__ float xs[64 * 68];
    __shared__ float wt[64 * 68];
    int r0 = blockIdx.x * 64;
    int b = r0 >> 11, t0 = r0 & 2047;
    int tid = threadIdx.x, tx = tid & 15, ty = tid >> 4;
    for (int h = 0; h < Hn; h++) {
        __syncthreads();
        for (int n = tid; n < 64 * 16; n += 256) {
            int row = n >> 4, c4 = n & 15;
            *(float4*)&xs[row * 68 + c4 * 4] =
                *(const float4*)(x + (size_t)(r0 + row) * En + h * 64 + c4 * 4);
        }
        for (int mm = 0; mm < 3; mm++) {
            const float* Wm = (mm == 0) ? Wq : (mm == 1) ? Wk : Wv;
            float* Om = (mm == 0) ? q : (mm == 1) ? k : v;
            __syncthreads();
            for (int n = tid; n < 64 * 16; n += 256) {
                int e = n >> 4, c4 = n & 15;
                float4 val = *(const float4*)(Wm + e * 64 + c4 * 4);
                wt[(c4 * 4 + 0) * 68 + e] = val.x;
                wt[(c4 * 4 + 1) * 68 + e] = val.y;
                wt[(c4 * 4 + 2) * 68 + e] = val.z;
                wt[(c4 * 4 + 3) * 68 + e] = val.w;
            }
            __syncthreads();
            float acc[4][4] = {};
            for (int d = 0; d < 64; d++) {
                float a0 = xs[(ty * 4 + 0) * 68 + d];
                float a1 = xs[(ty * 4 + 1) * 68 + d];
                float a2 = xs[(ty * 4 + 2) * 68 + d];
                float a3 = xs[(ty * 4 + 3) * 68 + d];
                float4 bv = *(const float4*)&wt[d * 68 + tx * 4];
                acc[0][0] += a0 * bv.x; acc[0][1] += a0 * bv.y; acc[0][2] += a0 * bv.z; acc[0][3] += a0 * bv.w;
                acc[1][0] += a1 * bv.x; acc[1][1] += a1 * bv.y; acc[1][2] += a1 * bv.z; acc[1][3] += a1 * bv.w;
                acc[2][0] += a2 * bv.x; acc[2][1] += a2 * bv.y; acc[2][2] += a2 * bv.z; acc[2][3] += a2 * bv.w;
                acc[3][0] += a3 * bv.x; acc[3][1] += a3 * bv.y; acc[3][2] += a3 * bv.z; acc[3][3] += a3 * bv.w;
            }
#pragma unroll
            for (int ri = 0; ri < 4; ri++) {
                size_t off = ((size_t)((b * Hn + h) * Tn + t0 + ty * 4 + ri)) * Dh + tx * 4;
                *(float4*)(Om + off) = make_float4(acc[ri][0], acc[ri][1], acc[ri][2], acc[ri][3]);
            }
        }
    }
}

// ---------------- tensor-core flash attention (raw-bit tf32, hoisted Q) -------------
#define ASTR 68
#define KOFF (128 * ASTR * 4)
#define VOFF (KOFF + 2 * 17408)
#define POFF (VOFF + 2 * 17408)
#define ATT_SMEM (POFF + 8 * 16 * ASTR * 4)
__global__ void __launch_bounds__(256) k_attn_tc(
    const float* __restrict__ q, const float* __restrict__ k,
    const float* __restrict__ v, float* __restrict__ o) {
    extern __shared__ float sm[];
    uint32_t sb = smem_u32(sm);
    int qt = blockIdx.x, hh = blockIdx.y, b = blockIdx.z;
    int tid = threadIdx.x, w = tid >> 5, l = tid & 31;
    int lg = l >> 2, lt = l & 3;

    const float* qb = q + ((size_t)(b * Hn + hh) * Tn + qt * 128) * Dh;
    const float* kb = k + ((size_t)(b * Hn + hh) * Tn) * Dh;
    const float* vb = v + ((size_t)(b * Hn + hh) * Tn) * Dh;

    {
        int r = tid >> 1, c = (tid & 1) * 32;
#pragma unroll
        for (int i = 0; i < 8; i++)
            *(float4*)&sm[r * ASTR + c + i * 4] = *(const float4*)(qb + r * 64 + c + i * 4);
    }
#define FILLKV(st, kt) do {                                                    \
    int _r = tid >> 2, _c = (tid & 3) * 16;                                    \
    const float* _kp = kb + ((size_t)(kt) * 64 + _r) * 64 + _c;                \
    const float* _vp = vb + ((size_t)(kt) * 64 + _r) * 64 + _c;                \
    uint32_t _dk = sb + KOFF + (st) * 17408 + (uint32_t)(_r * ASTR + _c) * 4;  \
    uint32_t _dv = sb + VOFF + (st) * 17408 + (uint32_t)(_r * ASTR + _c) * 4;  \
    _Pragma("unroll")                                                          \
    for (int _i = 0; _i < 4; _i++) {                                           \
        CP16(_dk + _i * 16, _kp + _i * 4);                                     \
        CP16(_dv + _i * 16, _vp + _i * 4);                                     \
    }                                                                          \
} while (0)

    FILLKV(0, 0);
    CPCOMMIT();
    __syncthreads();

    uint32_t qf[8][4];
#pragma unroll
    for (int ks = 0; ks < 8; ks++) {
        const float* qp = &sm[(w * 16 + lg) * ASTR + ks * 8 + lt];
        qf[ks][0] = frg(qp[0]);
        qf[ks][1] = frg(qp[8 * ASTR]);
        qf[ks][2] = frg(qp[4]);
        qf[ks][3] = frg(qp[8 * ASTR + 4]);
    }

    float m0 = NEG_HUGE, m1 = NEG_HUGE, l0 = 0.f, l1 = 0.f;
    float oacc[8][4];
#pragma unroll
    for (int nt = 0; nt < 8; nt++)
#pragma unroll
        for (int c = 0; c < 4; c++) oacc[nt][c] = 0.f;

    float* pw = sm + POFF / 4 + w * 16 * ASTR;
    int gr0 = qt * 128 + w * 16 + lg;
    int gr1 = gr0 + 8;

    int nkt = 2 * qt + 1;
    for (int kt = 0; kt <= nkt; kt++) {
        __syncthreads();
        if (kt + 1 <= nkt) {
            FILLKV((kt + 1) & 1, kt + 1);
            CPCOMMIT();
            CPWAIT1();
        } else {
            CPWAIT0();
        }
        __syncthreads();
        const float* Ks = sm + KOFF / 4 + (kt & 1) * 4352;
        const float* Vs = sm + VOFF / 4 + (kt & 1) * 4352;

        float sacc[8][4];
#pragma unroll
        for (int nt = 0; nt < 8; nt++)
#pragma unroll
            for (int c = 0; c < 4; c++) sacc[nt][c] = 0.f;
#pragma unroll
        for (int ks = 0; ks < 8; ks++) {
#pragma unroll
            for (int nt = 0; nt < 8; nt++) {
                uint32_t bf[2];
                const float* kp = &Ks[(nt * 8 + lg) * ASTR + ks * 8 + lt];
                bf[0] = frg(kp[0]);
                bf[1] = frg(kp[4]);
                mma_tf32(sacc[nt], qf[ks], bf);
            }
        }
        float mx0 = NEG_HUGE, mx1 = NEG_HUGE;
#pragma unroll
        for (int nt = 0; nt < 8; nt++) {
#pragma unroll
            for (int j = 0; j < 2; j++) {
                int gc = kt * 64 + nt * 8 + lt * 2 + j;
                float s0 = sacc[nt][j] * 0.125f;
                float s1 = sacc[nt][2 + j] * 0.125f;
                if (gc > gr0) s0 = NEG_HUGE;
                if (gc > gr1) s1 = NEG_HUGE;
                sacc[nt][j] = s0;
                sacc[nt][2 + j] = s1;
                mx0 = fmaxf(mx0, s0);
                mx1 = fmaxf(mx1, s1);
            }
        }
        mx0 = fmaxf(mx0, __shfl_xor_sync(0xffffffffu, mx0, 1));
        mx0 = fmaxf(mx0, __shfl_xor_sync(0xffffffffu, mx0, 2));
        mx1 = fmaxf(mx1, __shfl_xor_sync(0xffffffffu, mx1, 1));
        mx1 = fmaxf(mx1, __shfl_xor_sync(0xffffffffu, mx1, 2));
        float mn0 = fmaxf(m0, mx0), mn1 = fmaxf(m1, mx1);
        float cr0 = __expf(m0 - mn0), cr1 = __expf(m1 - mn1);
        m0 = mn0; m1 = mn1;
        float ps0 = 0.f, ps1 = 0.f;
#pragma unroll
        for (int nt = 0; nt < 8; nt++) {
#pragma unroll
            for (int j = 0; j < 2; j++) {
                float p0 = __expf(sacc[nt][j] - mn0);
                float p1 = __expf(sacc[nt][2 + j] - mn1);
                sacc[nt][j] = p0;
                sacc[nt][2 + j] = p1;
                ps0 += p0;
                ps1 += p1;
            }
        }
        ps0 += __shfl_xor_sync(0xffffffffu, ps0, 1);
        ps0 += __shfl_xor_sync(0xffffffffu, ps0, 2);
        ps1 += __shfl_xor_sync(0xffffffffu, ps1, 1);
        ps1 += __shfl_xor_sync(0xffffffffu, ps1, 2);
        l0 = l0 * cr0 + ps0;
        l1 = l1 * cr1 + ps1;
#pragma unroll
        for (int nt = 0; nt < 8; nt++) {
            oacc[nt][0] *= cr0; oacc[nt][1] *= cr0;
            oacc[nt][2] *= cr1; oacc[nt][3] *= cr1;
        }
#pragma unroll
        for (int nt = 0; nt < 8; nt++) {
            *(float2*)&pw[lg * ASTR + nt * 8 + lt * 2] = make_float2(sacc[nt][0], sacc[nt][1]);
            *(float2*)&pw[(lg + 8) * ASTR + nt * 8 + lt * 2] = make_float2(sacc[nt][2], sacc[nt][3]);
        }
        __syncwarp();
#pragma unroll
        for (int ks = 0; ks < 8; ks++) {
            uint32_t af[4];
            const float* pp = &pw[lg * ASTR + ks * 8 + lt];
            af[0] = frg(pp[0]);
            af[1] = frg(pp[8 * ASTR]);
            af[2] = frg(pp[4]);
            af[3] = frg(pp[8 * ASTR + 4]);
#pragma unroll
            for (int nt = 0; nt < 8; nt++) {
                uint32_t bf[2];
                const float* vp = &Vs[(ks * 8 + lt) * ASTR + nt * 8 + lg];
                bf[0] = frg(vp[0]);
                bf[1] = frg(vp[4 * ASTR]);
                mma_tf32(oacc[nt], af, bf);
            }
        }
        __syncwarp();
    }
    float inv0 = 1.f / l0, inv1 = 1.f / l1;
    size_t base0 = ((size_t)(b * Tn) + gr0) * En + hh * 64;
    size_t base1 = base0 + (size_t)8 * En;
#pragma unroll
    for (int nt = 0; nt < 8; nt++) {
        int cc = nt * 8 + lt * 2;
        *(float2*)(o + base0 + cc) = make_float2(oacc[nt][0] * inv0, oacc[nt][1] * inv0);
        *(float2*)(o + base1 + cc) = make_float2(oacc[nt][2] * inv1, oacc[nt][3] * inv1);
    }
}

// ---------------- tf32 single-pass GEMM: Y = X @ W^T + bias (optional GELU) ---------
#define FSTR 36
#define FMATB (128 * FSTR * 4)
#define FBUFB (2 * FMATB)
template <int ACT>
__global__ void __launch_bounds__(256, 2) k_gemm32(
    const float* __restrict__ X, const float* __restrict__ W,
    const float* __restrict__ bias, float* __restrict__ Y, int M, int N, int K) {
    extern __shared__ char dsm[];
    uint32_t sb = smem_u32(dsm);
    int tid = threadIdx.x, wid = tid >> 5, lane = tid & 31;
    int bm = blockIdx.x * 128, bn = blockIdx.y * 128;
    int wm = (wid >> 2) * 64, wn = (wid & 3) * 32;
    float acc[4][4][4];
#pragma unroll
    for (int a = 0; a < 4; a++)
#pragma unroll
        for (int b = 0; b < 4; b++)
#pragma unroll
            for (int c = 0; c < 4; c++) acc[a][b][c] = 0.f;
    int NK = K >> 5;
#define F32FILL(bsel, kc) do {                                                \
    uint32_t _b = sb + (bsel) * FBUFB;                                        \
    int _k0 = (kc) * 32;                                                      \
    _Pragma("unroll")                                                         \
    for (int it = 0; it < 4; it++) {                                          \
        int _i = tid + it * 256;                                              \
        int _r = _i >> 3, _c = (_i & 7) * 4;                                  \
        CP16(_b + (uint32_t)(_r * FSTR + _c) * 4, X + (size_t)(bm + _r) * K + _k0 + _c); \
        CP16(_b + FMATB + (uint32_t)(_r * FSTR + _c) * 4, W + (size_t)(bn + _r) * K + _k0 + _c); \
    }                                                                         \
} while (0)
    F32FILL(0, 0);
    CPCOMMIT();
    for (int kc = 0; kc < NK; kc++) {
        CPWAIT0();
        __syncthreads();
        if (kc + 1 < NK) {
            F32FILL((kc + 1) & 1, kc + 1);
            CPCOMMIT();
        }
        const float* fA = (const float*)(dsm + (kc & 1) * FBUFB);
        const float* fB = (const float*)(dsm + (kc & 1) * FBUFB + FMATB);
#pragma unroll
        for (int ks = 0; ks < 4; ks++) {
            uint32_t a[4][4], b[4][2];
#pragma unroll
            for (int mt = 0; mt < 4; mt++) {
                const float* pa = fA + (wm + mt * 16 + (lane >> 2)) * FSTR + ks * 8 + (lane & 3);
                a[mt][0] = to_tf32(pa[0]);
                a[mt][1] = to_tf32(pa[8 * FSTR]);
                a[mt][2] = to_tf32(pa[4]);
                a[mt][3] = to_tf32(pa[8 * FSTR + 4]);
            }
#pragma unroll
            for (int nt = 0; nt < 4; nt++) {
                const float* pb = fB + (wn + nt * 8 + (lane >> 2)) * FSTR + ks * 8 + (lane & 3);
                b[nt][0] = to_tf32(pb[0]);
                b[nt][1] = to_tf32(pb[4]);
            }
#pragma unroll
            for (int mt = 0; mt < 4; mt++)
#pragma unroll
                for (int nt = 0; nt < 4; nt++) mma_tf32(acc[mt][nt], a[mt], b[nt]);
        }
    }
#pragma unroll
    for (int mt = 0; mt < 4; mt++) {
#pragma unroll
        for (int nt = 0; nt < 4; nt++) {
            int rr = bm + wm + mt * 16 + (lane >> 2);
            int cc = bn + wn + nt * 8 + (lane & 3) * 2;
            float b0 = __ldg(bias + cc), b1 = __ldg(bias + cc + 1);
            float v0 = acc[mt][nt][0] + b0, v1 = acc[mt][nt][1] + b1;
            float v2 = acc[mt][nt][2] + b0, v3 = acc[mt][nt][3] + b1;
            if (ACT) {
                v0 = 0.5f * v0 * (1.0f + erff(v0 * 0.70710678f));
                v1 = 0.5f * v1 * (1.0f + erff(v1 * 0.70710678f));
                v2 = 0.5f * v2 * (1.0f + erff(v2 * 0.70710678f));
                v3 = 0.5f * v3 * (1.0f + erff(v3 * 0.70710678f));
            }
            *(float2*)(Y + (size_t)rr * N + cc) = make_float2(v0, v1);
            *(float2*)(Y + (size_t)(rr + 8) * N + cc) = make_float2(v2, v3);
        }
    }
}

// ---------------- residual add + layernorm (fp32 only) ----------------
__global__ void k_addln(const float* __restrict__ a, const float* __restrict__ res,
                        const float* __restrict__ g, const float* __restrict__ bta,
                        float* __restrict__ out, int hasres) {
    int row = blockIdx.x, t = threadIdx.x;
    float4 vv = ((const float4*)(a + (size_t)row * En))[t];
    if (hasres) {
        float4 r = ((const float4*)(res + (size_t)row * En))[t];
        vv.x += r.x; vv.y += r.y; vv.z += r.z; vv.w += r.w;
    }
    float s1 = vv.x + vv.y + vv.z + vv.w;
    float s2 = vv.x * vv.x + vv.y * vv.y + vv.z * vv.z + vv.w * vv.w;
#pragma unroll
    for (int off = 16; off; off >>= 1) {
        s1 += __shfl_down_sync(0xffffffffu, s1, off);
        s2 += __shfl_down_sync(0xffffffffu, s2, off);
    }
    __shared__ float r1[8], r2[8];
    __shared__ float bmean, brs;
    int w = t >> 5, lane = t & 31;
    if (lane == 0) { r1[w] = s1; r2[w] = s2; }
    __syncthreads();
    if (t == 0) {
        float a1 = 0.f, a2 = 0.f;
#pragma unroll
        for (int i2 = 0; i2 < 8; i2++) { a1 += r1[i2]; a2 += r2[i2]; }
        float mean = a1 * (1.0f / En);
        bmean = mean;
        brs = rsqrtf(a2 * (1.0f / En) - mean * mean + 1e-5f);
    }
    __syncthreads();
    float mean = bmean, rs = brs;
    float4 gg = ((const float4*)g)[t];
    float4 bb = ((const float4*)bta)[t];
    float4 o;
    o.x = (vv.x - mean) * rs * gg.x + bb.x;
    o.y = (vv.y - mean) * rs * gg.y + bb.y;
    o.z = (vv.z - mean) * rs * gg.z + bb.z;
    o.w = (vv.w - mean) * rs * gg.w + bb.w;
    ((float4*)(out + (size_t)row * En))[t] = o;
}

// ---------------- loss ----------------
__device__ __forceinline__ void lse_acc(float& m, float& s, float xv) {
    if (xv <= m) s += __expf(xv - m);
    else { s = s * __expf(m - xv) + 1.f; m = xv; }
}
__device__ __forceinline__ void lse_merge(float& m, float& s, float mo, float so) {
    float M = fmaxf(m, mo);
    s = s * __expf(m - M) + so * __expf(mo - M);
    m = M;
}
__global__ void k_rowloss(const float* __restrict__ logits, const void* __restrict__ tgt,
                          float* __restrict__ rl) {
    int row = blockIdx.x, t = threadIdx.x;
    const float* lp = logits + (size_t)row * Vn;
    float m = NEG_HUGE, s = 0.f;
    for (int c = 4 * t; c < Vn; c += 1024) {
        float4 vv = *(const float4*)(lp + c);
        lse_acc(m, s, vv.x); lse_acc(m, s, vv.y); lse_acc(m, s, vv.z); lse_acc(m, s, vv.w);
    }
#pragma unroll
    for (int off = 16; off; off >>= 1) {
        float mo = __shfl_down_sync(0xffffffffu, m, off);
        float so = __shfl_down_sync(0xffffffffu, s, off);
        lse_merge(m, s, mo, so);
    }
    __shared__ float rm[8], rs2[8];
    int w = t >> 5, lane = t & 31;
    if (lane == 0) { rm[w] = m; rs2[w] = s; }
    __syncthreads();
    if (t == 0) {
#pragma unroll
        for (int i2 = 1; i2 < 8; i2++) lse_merge(rm[0], rs2[0], rm[i2], rs2[i2]);
        bool is64 = tok_is64(tgt);
        int tv = tok_at(tgt, row, is64);
        rl[row] = (rm[0] + logf(rs2[0])) - lp[tv];
    }
}
__global__ void k_lossfinal(const float* __restrict__ rl, float* __restrict__ dst) {
    int t = threadIdx.x;
    float s = 0.f;
    for (int i = t; i < Rn; i += 256) s += rl[i];
#pragma unroll
    for (int off = 16; off; off >>= 1) s += __shfl_down_sync(0xffffffffu, s, off);
    __shared__ float red[8];
    int w = t >> 5, lane = t & 31;
    if (lane == 0) red[w] = s;
    __syncthreads();
    if (t == 0) {
        float a = 0.f;
#pragma unroll
        for (int i2 = 0; i2 < 8; i2++) a += red[i2];
        dst[0] = a * (1.0f / Rn);
    }
}

extern "C" void kernel_launch(void* const* d_in, const int* in_sizes, int n_in,
                              void* d_out, int out_size) {
    const void* idx = d_in[0];
    const void* tgt = d_in[1];
    const float* tok = (const float*)d_in[2];
    const float* pos = (const float*)d_in[3];
    const float* Wq = (const float*)d_in[4];
    const float* Wk = (const float*)d_in[5];
    const float* Wv = (const float*)d_in[6];
    const float* Wo = (const float*)d_in[7];
    const float* bo = (const float*)d_in[8];
    const float* ln1g = (const float*)d_in[9];
    const float* ln1b = (const float*)d_in[10];
    const float* W1 = (const float*)d_in[11];
    const float* b1 = (const float*)d_in[12];
    const float* W2 = (const float*)d_in[13];
    const float* b2 = (const float*)d_in[14];
    const float* ln2g = (const float*)d_in[15];
    const float* ln2b = (const float*)d_in[16];
    const float* lnfg = (const float*)d_in[17];
    const float* lnfb = (const float*)d_in[18];
    const float* lmw = (const float*)d_in[19];
    const float* lmb = (const float*)d_in[20];
    float* out = (float*)d_out;

    float *x, *tmp, *q, *k, *v, *att, *h, *rl;
    cudaGetSymbolAddress((void**)&x, g_x);
    cudaGetSymbolAddress((void**)&tmp, g_tmp);
    cudaGetSymbolAddress((void**)&q, g_q);
    cudaGetSymbolAddress((void**)&k, g_k);
    cudaGetSymbolAddress((void**)&v, g_v);
    cudaGetSymbolAddress((void**)&att, g_att);
    cudaGetSymbolAddress((void**)&h, g_h);
    cudaGetSymbolAddress((void**)&rl, g_rl);

    cudaFuncSetAttribute(k_attn_tc, cudaFuncAttributeMaxDynamicSharedMemorySize, ATT_SMEM);
    const int f32_smem = 2 * FBUFB;
    cudaFuncSetAttribute(k_gemm32<0>, cudaFuncAttributeMaxDynamicSharedMemorySize, f32_smem);
    cudaFuncSetAttribute(k_gemm32<1>, cudaFuncAttributeMaxDynamicSharedMemorySize, f32_smem);

    k_embed<<<Rn, 256>>>(idx, tok, pos, x);
    for (int l = 0; l < Ln; l++) {
        k_qkv<<<Rn / 64, 256>>>(x, Wq + (size_t)l * Dh * Dh, Wk + (size_t)l * Dh * Dh,
                                Wv + (size_t)l * Dh * Dh, q, k, v);
        k_attn_tc<<<dim3(Tn / 128, Hn, Bn), 256, ATT_SMEM>>>(q, k, v, att);
        k_gemm32<0><<<dim3(Rn / 128, En / 128), 256, f32_smem>>>(
            att, Wo + (size_t)l * En * En, bo + (size_t)l * En, tmp, Rn, En, En);
        k_addln<<<Rn, 256>>>(tmp, x, ln1g + (size_t)l * En, ln1b + (size_t)l * En, x, 1);
        k_gemm32<1><<<dim3(Rn / 128, FFn / 128), 256, f32_smem>>>(
            x, W1 + (size_t)l * FFn * En, b1 + (size_t)l * FFn, h, Rn, FFn, En);
        k_gemm32<0><<<dim3(Rn / 128, En / 128), 256, f32_smem>>>(
            h, W2 + (size_t)l * En * FFn, b2 + (size_t)l * En, tmp, Rn, En, FFn);
        k_addln<<<Rn, 256>>>(tmp, x, ln2g + (size_t)l * En, ln2b + (size_t)l * En, x, 1);
    }
    k_addln<<<Rn, 256>>>(x, x, lnfg, lnfb, x, 0);
    k_gemm32<0><<<dim3(Rn / 128, Vn / 128), 256, f32_smem>>>(x, lmw, lmb, out, Rn, Vn, En);
    if ((long long)out_size > (long long)Rn * Vn) {
        k_rowloss<<<Rn, 256>>>(out, tgt, rl);
        k_lossfinal<<<1, 256>>>(rl, out + (size_t)Rn * Vn);
    }
}

// round 16
// speedup vs baseline: 1.1984x; 1.1037x over previous
#include <cuda_runtime.h>
#include <cuda_bf16.h>
#include <math.h>
#include <stdint.h>

#define Bn 4
#define Tn 2048
#define En 1024
#define Hn 16
#define Dh 64
#define Ln 4
#define FFn 4096
#define Vn 32000
#define Rn 8192
#define NEG_HUGE (-1e30f)

__device__ float g_x[Rn * En];
__device__ float g_xr[Rn * En];
__device__ float g_tmp[Rn * En];
__device__ float g_q[Rn * En];
__device__ float g_k[Rn * En];
__device__ float g_v[Rn * En];
__device__ float g_att[Rn * En];
__device__ float g_h[(size_t)Rn * FFn];
__device__ float g_wor[(size_t)Ln * En * En];
__device__ float g_w1r[(size_t)Ln * FFn * En];
__device__ float g_w2r[(size_t)Ln * En * FFn];
__device__ float g_lmwr[(size_t)Vn * En];
__device__ float g_rl[Rn];

// ---------------- helpers ----------------
__device__ __forceinline__ uint32_t smem_u32(const void* p) {
    uint32_t a;
    asm("{ .reg .u64 t; cvta.to.shared.u64 t, %1; cvt.u32.u64 %0, t; }" : "=r"(a) : "l"(p));
    return a;
}
__device__ __forceinline__ void mma_tf32(float* c, const uint32_t* a, const uint32_t* b) {
    asm volatile("mma.sync.aligned.m16n8k8.row.col.f32.tf32.tf32.f32 "
                 "{%0,%1,%2,%3}, {%4,%5,%6,%7}, {%8,%9}, {%0,%1,%2,%3};"
                 : "+f"(c[0]), "+f"(c[1]), "+f"(c[2]), "+f"(c[3])
                 : "r"(a[0]), "r"(a[1]), "r"(a[2]), "r"(a[3]), "r"(b[0]), "r"(b[1]));
}
__device__ __forceinline__ uint32_t to_tf32(float f) {
    uint32_t r;
    asm("cvt.rna.tf32.f32 %0, %1;" : "=r"(r) : "f"(f));
    return r;
}
// RNA-round to tf32 grid; result is exact fp32 with low mantissa bits zero
__device__ __forceinline__ float rnd32(float f) { return __uint_as_float(to_tf32(f)); }
__device__ __forceinline__ uint32_t frg(float f) { return __float_as_uint(f); }
#define CP16(dst, src) asm volatile("cp.async.cg.shared.global [%0], [%1], 16;" \
    :: "r"(dst), "l"(__cvta_generic_to_global(src)) : "memory")
#define CPCOMMIT() asm volatile("cp.async.commit_group;" ::: "memory")
#define CPWAIT1() asm volatile("cp.async.wait_group 1;" ::: "memory")
#define CPWAIT0() asm volatile("cp.async.wait_group 0;" ::: "memory")

__device__ __forceinline__ bool tok_is64(const void* p) {
    const unsigned long long* q = (const unsigned long long*)p;
    unsigned long long acc = 0ull;
#pragma unroll
    for (int i = 0; i < 8; i++) acc |= (q[i] & 0xFFFFFFFF00000000ull);
    return acc == 0ull;
}
__device__ __forceinline__ int tok_at(const void* p, int i, bool is64) {
    return is64 ? (int)((const long long*)p)[i] : ((const int*)p)[i];
}

// ---------------- weight pre-round (fp32 -> tf32 grid) ----------------
__global__ void k_round(const float* __restrict__ s, float* __restrict__ d, int n4) {
    int i = blockIdx.x * 256 + threadIdx.x;
    if (i >= n4) return;
    float4 v = ((const float4*)s)[i];
    ((float4*)d)[i] = make_float4(rnd32(v.x), rnd32(v.y), rnd32(v.z), rnd32(v.w));
}

// ---------------- embedding ----------------
__global__ void k_embed(const void* __restrict__ idx, const float* __restrict__ tok,
                        const float* __restrict__ pos, float* __restrict__ x) {
    int row = blockIdx.x, t = threadIdx.x;
    bool is64 = tok_is64(idx);
    int token = tok_at(idx, row, is64);
    int tt = row & (Tn - 1);
    float4 a = ((const float4*)(tok + (size_t)token * En))[t];
    float4 p = ((const float4*)(pos + (size_t)tt * En))[t];
    ((float4*)(x + (size_t)row * En))[t] = make_float4(a.x + p.x, a.y + p.y, a.z + p.z, a.w + p.w);
}

// ---------------- QKV (fp32) ----------------
__global__ void __launch_bounds__(256) k_qkv(
    const float* __restrict__ x, const float* __restrict__ Wq,
    const float* __restrict__ Wk, const float* __restrict__ Wv,
    float* __restrict__ q, float* __restrict__ k, float* __restrict__ v) {
    __shared__ float xs[64 * 68];
    __shared__ float wt[64 * 68];
    int r0 = blockIdx.x * 64;
    int b = r0 >> 11, t0 = r0 & 2047;
    int tid = threadIdx.x, tx = tid & 15, ty = tid >> 4;
    for (int h = 0; h < Hn; h++) {
        __syncthreads();
        for (int n = tid; n < 64 * 16; n += 256) {
            int row = n >> 4, c4 = n & 15;
            *(float4*)&xs[row * 68 + c4 * 4] =
                *(const float4*)(x + (size_t)(r0 + row) * En + h * 64 + c4 * 4);
        }
        for (int mm = 0; mm < 3; mm++) {
            const float* Wm = (mm == 0) ? Wq : (mm == 1) ? Wk : Wv;
            float* Om = (mm == 0) ? q : (mm == 1) ? k : v;
            __syncthreads();
            for (int n = tid; n < 64 * 16; n += 256) {
                int e = n >> 4, c4 = n & 15;
                float4 val = *(const float4*)(Wm + e * 64 + c4 * 4);
                wt[(c4 * 4 + 0) * 68 + e] = val.x;
                wt[(c4 * 4 + 1) * 68 + e] = val.y;
                wt[(c4 * 4 + 2) * 68 + e] = val.z;
                wt[(c4 * 4 + 3) * 68 + e] = val.w;
            }
            __syncthreads();
            float acc[4][4] = {};
            for (int d = 0; d < 64; d++) {
                float a0 = xs[(ty * 4 + 0) * 68 + d];
                float a1 = xs[(ty * 4 + 1) * 68 + d];
                float a2 = xs[(ty * 4 + 2) * 68 + d];
                float a3 = xs[(ty * 4 + 3) * 68 + d];
                float4 bv = *(const float4*)&wt[d * 68 + tx * 4];
                acc[0][0] += a0 * bv.x; acc[0][1] += a0 * bv.y; acc[0][2] += a0 * bv.z; acc[0][3] += a0 * bv.w;
                acc[1][0] += a1 * bv.x; acc[1][1] += a1 * bv.y; acc[1][2] += a1 * bv.z; acc[1][3] += a1 * bv.w;
                acc[2][0] += a2 * bv.x; acc[2][1] += a2 * bv.y; acc[2][2] += a2 * bv.z; acc[2][3] += a2 * bv.w;
                acc[3][0] += a3 * bv.x; acc[3][1] += a3 * bv.y; acc[3][2] += a3 * bv.z; acc[3][3] += a3 * bv.w;
            }
#pragma unroll
            for (int ri = 0; ri < 4; ri++) {
                size_t off = ((size_t)((b * Hn + h) * Tn + t0 + ty * 4 + ri)) * Dh + tx * 4;
                *(float4*)(Om + off) = make_float4(acc[ri][0], acc[ri][1], acc[ri][2], acc[ri][3]);
            }
        }
    }
}

// ---------------- tensor-core flash attention (raw-bit tf32, hoisted Q) -------------
#define ASTR 68
#define KOFF (128 * ASTR * 4)
#define VOFF (KOFF + 2 * 17408)
#define POFF (VOFF + 2 * 17408)
#define ATT_SMEM (POFF + 8 * 16 * ASTR * 4)
__global__ void __launch_bounds__(256) k_attn_tc(
    const float* __restrict__ q, const float* __restrict__ k,
    const float* __restrict__ v, float* __restrict__ o) {
    extern __shared__ float sm[];
    uint32_t sb = smem_u32(sm);
    int qt = blockIdx.x, hh = blockIdx.y, b = blockIdx.z;
    int tid = threadIdx.x, w = tid >> 5, l = tid & 31;
    int lg = l >> 2, lt = l & 3;

    const float* qb = q + ((size_t)(b * Hn + hh) * Tn + qt * 128) * Dh;
    const float* kb = k + ((size_t)(b * Hn + hh) * Tn) * Dh;
    const float* vb = v + ((size_t)(b * Hn + hh) * Tn) * Dh;

    {
        int r = tid >> 1, c = (tid & 1) * 32;
#pragma unroll
        for (int i = 0; i < 8; i++)
            *(float4*)&sm[r * ASTR + c + i * 4] = *(const float4*)(qb + r * 64 + c + i * 4);
    }
#define FILLKV(st, kt) do {                                                    \
    int _r = tid >> 2, _c = (tid & 3) * 16;                                    \
    const float* _kp = kb + ((size_t)(kt) * 64 + _r) * 64 + _c;                \
    const float* _vp = vb + ((size_t)(kt) * 64 + _r) * 64 + _c;                \
    uint32_t _dk = sb + KOFF + (st) * 17408 + (uint32_t)(_r * ASTR + _c) * 4;  \
    uint32_t _dv = sb + VOFF + (st) * 17408 + (uint32_t)(_r * ASTR + _c) * 4;  \
    _Pragma("unroll")                                                          \
    for (int _i = 0; _i < 4; _i++) {                                           \
        CP16(_dk + _i * 16, _kp + _i * 4);                                     \
        CP16(_dv + _i * 16, _vp + _i * 4);                                     \
    }                                                                          \
} while (0)

    FILLKV(0, 0);
    CPCOMMIT();
    __syncthreads();

    uint32_t qf[8][4];
#pragma unroll
    for (int ks = 0; ks < 8; ks++) {
        const float* qp = &sm[(w * 16 + lg) * ASTR + ks * 8 + lt];
        qf[ks][0] = frg(qp[0]);
        qf[ks][1] = frg(qp[8 * ASTR]);
        qf[ks][2] = frg(qp[4]);
        qf[ks][3] = frg(qp[8 * ASTR + 4]);
    }

    float m0 = NEG_HUGE, m1 = NEG_HUGE, l0 = 0.f, l1 = 0.f;
    float oacc[8][4];
#pragma unroll
    for (int nt = 0; nt < 8; nt++)
#pragma unroll
        for (int c = 0; c < 4; c++) oacc[nt][c] = 0.f;

    float* pw = sm + POFF / 4 + w * 16 * ASTR;
    int gr0 = qt * 128 + w * 16 + lg;
    int gr1 = gr0 + 8;

    int nkt = 2 * qt + 1;
    for (int kt = 0; kt <= nkt; kt++) {
        __syncthreads();
        if (kt + 1 <= nkt) {
            FILLKV((kt + 1) & 1, kt + 1);
            CPCOMMIT();
            CPWAIT1();
        } else {
            CPWAIT0();
        }
        __syncthreads();
        const float* Ks = sm + KOFF / 4 + (kt & 1) * 4352;
        const float* Vs = sm + VOFF / 4 + (kt & 1) * 4352;

        float sacc[8][4];
#pragma unroll
        for (int nt = 0; nt < 8; nt++)
#pragma unroll
            for (int c = 0; c < 4; c++) sacc[nt][c] = 0.f;
#pragma unroll
        for (int ks = 0; ks < 8; ks++) {
#pragma unroll
            for (int nt = 0; nt < 8; nt++) {
                uint32_t bf[2];
                const float* kp = &Ks[(nt * 8 + lg) * ASTR + ks * 8 + lt];
                bf[0] = frg(kp[0]);
                bf[1] = frg(kp[4]);
                mma_tf32(sacc[nt], qf[ks], bf);
            }
        }
        float mx0 = NEG_HUGE, mx1 = NEG_HUGE;
#pragma unroll
        for (int nt = 0; nt < 8; nt++) {
#pragma unroll
            for (int j = 0; j < 2; j++) {
                int gc = kt * 64 + nt * 8 + lt * 2 + j;
                float s0 = sacc[nt][j] * 0.125f;
                float s1 = sacc[nt][2 + j] * 0.125f;
                if (gc > gr0) s0 = NEG_HUGE;
                if (gc > gr1) s1 = NEG_HUGE;
                sacc[nt][j] = s0;
                sacc[nt][2 + j] = s1;
                mx0 = fmaxf(mx0, s0);
                mx1 = fmaxf(mx1, s1);
            }
        }
        mx0 = fmaxf(mx0, __shfl_xor_sync(0xffffffffu, mx0, 1));
        mx0 = fmaxf(mx0, __shfl_xor_sync(0xffffffffu, mx0, 2));
        mx1 = fmaxf(mx1, __shfl_xor_sync(0xffffffffu, mx1, 1));
        mx1 = fmaxf(mx1, __shfl_xor_sync(0xffffffffu, mx1, 2));
        float mn0 = fmaxf(m0, mx0), mn1 = fmaxf(m1, mx1);
        float cr0 = __expf(m0 - mn0), cr1 = __expf(m1 - mn1);
        m0 = mn0; m1 = mn1;
        float ps0 = 0.f, ps1 = 0.f;
#pragma unroll
        for (int nt = 0; nt < 8; nt++) {
#pragma unroll
            for (int j = 0; j < 2; j++) {
                float p0 = __expf(sacc[nt][j] - mn0);
                float p1 = __expf(sacc[nt][2 + j] - mn1);
                sacc[nt][j] = p0;
                sacc[nt][2 + j] = p1;
                ps0 += p0;
                ps1 += p1;
            }
        }
        ps0 += __shfl_xor_sync(0xffffffffu, ps0, 1);
        ps0 += __shfl_xor_sync(0xffffffffu, ps0, 2);
        ps1 += __shfl_xor_sync(0xffffffffu, ps1, 1);
        ps1 += __shfl_xor_sync(0xffffffffu, ps1, 2);
        l0 = l0 * cr0 + ps0;
        l1 = l1 * cr1 + ps1;
#pragma unroll
        for (int nt = 0; nt < 8; nt++) {
            oacc[nt][0] *= cr0; oacc[nt][1] *= cr0;
            oacc[nt][2] *= cr1; oacc[nt][3] *= cr1;
        }
#pragma unroll
        for (int nt = 0; nt < 8; nt++) {
            *(float2*)&pw[lg * ASTR + nt * 8 + lt * 2] = make_float2(sacc[nt][0], sacc[nt][1]);
            *(float2*)&pw[(lg + 8) * ASTR + nt * 8 + lt * 2] = make_float2(sacc[nt][2], sacc[nt][3]);
        }
        __syncwarp();
#pragma unroll
        for (int ks = 0; ks < 8; ks++) {
            uint32_t af[4];
            const float* pp = &pw[lg * ASTR + ks * 8 + lt];
            af[0] = frg(pp[0]);
            af[1] = frg(pp[8 * ASTR]);
            af[2] = frg(pp[4]);
            af[3] = frg(pp[8 * ASTR + 4]);
#pragma unroll
            for (int nt = 0; nt < 8; nt++) {
                uint32_t bf[2];
                const float* vp = &Vs[(ks * 8 + lt) * ASTR + nt * 8 + lg];
                bf[0] = frg(vp[0]);
                bf[1] = frg(vp[4 * ASTR]);
                mma_tf32(oacc[nt], af, bf);
            }
        }
        __syncwarp();
    }
    // epilogue: normalize + RNA-round to tf32 grid (att feeds Wo GEMM via frg)
    float inv0 = 1.f / l0, inv1 = 1.f / l1;
    size_t base0 = ((size_t)(b * Tn) + gr0) * En + hh * 64;
    size_t base1 = base0 + (size_t)8 * En;
#pragma unroll
    for (int nt = 0; nt < 8; nt++) {
        int cc = nt * 8 + lt * 2;
        *(float2*)(o + base0 + cc) = make_float2(rnd32(oacc[nt][0] * inv0), rnd32(oacc[nt][1] * inv0));
        *(float2*)(o + base1 + cc) = make_float2(rnd32(oacc[nt][2] * inv1), rnd32(oacc[nt][3] * inv1));
    }
}

// ---------------- tf32 single-pass GEMM (pre-rounded inputs, raw-bit operands) ------
// ROUND=1: round outputs to tf32 grid (when output feeds another GEMM)
#define FSTR 36
#define FMATB (128 * FSTR * 4)
#define FBUFB (2 * FMATB)
template <int ACT, int ROUND>
__global__ void __launch_bounds__(256, 2) k_gemm32(
    const float* __restrict__ X, const float* __restrict__ W,
    const float* __restrict__ bias, float* __restrict__ Y, int M, int N, int K) {
    extern __shared__ char dsm[];
    uint32_t sb = smem_u32(dsm);
    int tid = threadIdx.x, wid = tid >> 5, lane = tid & 31;
    int bm = blockIdx.x * 128, bn = blockIdx.y * 128;
    int wm = (wid >> 2) * 64, wn = (wid & 3) * 32;
    float acc[4][4][4];
#pragma unroll
    for (int a = 0; a < 4; a++)
#pragma unroll
        for (int b = 0; b < 4; b++)
#pragma unroll
            for (int c = 0; c < 4; c++) acc[a][b][c] = 0.f;
    int NK = K >> 5;
#define F32FILL(bsel, kc) do {                                                \
    uint32_t _b = sb + (bsel) * FBUFB;                                        \
    int _k0 = (kc) * 32;                                                      \
    _Pragma("unroll")                                                         \
    for (int it = 0; it < 4; it++) {                                          \
        int _i = tid + it * 256;                                              \
        int _r = _i >> 3, _c = (_i & 7) * 4;                                  \
        CP16(_b + (uint32_t)(_r * FSTR + _c) * 4, X + (size_t)(bm + _r) * K + _k0 + _c); \
        CP16(_b + FMATB + (uint32_t)(_r * FSTR + _c) * 4, W + (size_t)(bn + _r) * K + _k0 + _c); \
    }                                                                         \
} while (0)
    F32FILL(0, 0);
    CPCOMMIT();
    for (int kc = 0; kc < NK; kc++) {
        CPWAIT0();
        __syncthreads();
        if (kc + 1 < NK) {
            F32FILL((kc + 1) & 1, kc + 1);
            CPCOMMIT();
        }
        const float* fA = (const float*)(dsm + (kc & 1) * FBUFB);
        const float* fB = (const float*)(dsm + (kc & 1) * FBUFB + FMATB);
#pragma unroll
        for (int ks = 0; ks < 4; ks++) {
            uint32_t a[4][4], b[4][2];
#pragma unroll
            for (int mt = 0; mt < 4; mt++) {
                const float* pa = fA + (wm + mt * 16 + (lane >> 2)) * FSTR + ks * 8 + (lane & 3);
                a[mt][0] = frg(pa[0]);
                a[mt][1] = frg(pa[8 * FSTR]);
                a[mt][2] = frg(pa[4]);
                a[mt][3] = frg(pa[8 * FSTR + 4]);
            }
#pragma unroll
            for (int nt = 0; nt < 4; nt++) {
                const float* pb = fB + (wn + nt * 8 + (lane >> 2)) * FSTR + ks * 8 + (lane & 3);
                b[nt][0] = frg(pb[0]);
                b[nt][1] = frg(pb[4]);
            }
#pragma unroll
            for (int mt = 0; mt < 4; mt++)
#pragma unroll
                for (int nt = 0; nt < 4; nt++) mma_tf32(acc[mt][nt], a[mt], b[nt]);
        }
    }
#pragma unroll
    for (int mt = 0; mt < 4; mt++) {
#pragma unroll
        for (int nt = 0; nt < 4; nt++) {
            int rr = bm + wm + mt * 16 + (lane >> 2);
            int cc = bn + wn + nt * 8 + (lane & 3) * 2;
            float b0 = __ldg(bias + cc), b1 = __ldg(bias + cc + 1);
            float v0 = acc[mt][nt][0] + b0, v1 = acc[mt][nt][1] + b1;
            float v2 = acc[mt][nt][2] + b0, v3 = acc[mt][nt][3] + b1;
            if (ACT) {
                v0 = 0.5f * v0 * (1.0f + erff(v0 * 0.70710678f));
                v1 = 0.5f * v1 * (1.0f + erff(v1 * 0.70710678f));
                v2 = 0.5f * v2 * (1.0f + erff(v2 * 0.70710678f));
                v3 = 0.5f * v3 * (1.0f + erff(v3 * 0.70710678f));
            }
            if (ROUND) {
                v0 = rnd32(v0); v1 = rnd32(v1); v2 = rnd32(v2); v3 = rnd32(v3);
            }
            *(float2*)(Y + (size_t)rr * N + cc) = make_float2(v0, v1);
            *(float2*)(Y + (size_t)(rr + 8) * N + cc) = make_float2(v2, v3);
        }
    }
}

// ---------------- residual add + layernorm; optional rounded copy -------------------
__global__ void k_addln(const float* __restrict__ a, const float* __restrict__ res,
                        const float* __restrict__ g, const float* __restrict__ bta,
                        float* __restrict__ out, float* __restrict__ outr, int hasres) {
    int row = blockIdx.x, t = threadIdx.x;
    float4 vv = ((const float4*)(a + (size_t)row * En))[t];
    if (hasres) {
        float4 r = ((const float4*)(res + (size_t)row * En))[t];
        vv.x += r.x; vv.y += r.y; vv.z += r.z; vv.w += r.w;
    }
    float s1 = vv.x + vv.y + vv.z + vv.w;
    float s2 = vv.x * vv.x + vv.y * vv.y + vv.z * vv.z + vv.w * vv.w;
#pragma unroll
    for (int off = 16; off; off >>= 1) {
        s1 += __shfl_down_sync(0xffffffffu, s1, off);
        s2 += __shfl_down_sync(0xffffffffu, s2, off);
    }
    __shared__ float r1[8], r2[8];
    __shared__ float bmean, brs;
    int w = t >> 5, lane = t & 31;
    if (lane == 0) { r1[w] = s1; r2[w] = s2; }
    __syncthreads();
    if (t == 0) {
        float a1 = 0.f, a2 = 0.f;
#pragma unroll
        for (int i2 = 0; i2 < 8; i2++) { a1 += r1[i2]; a2 += r2[i2]; }
        float mean = a1 * (1.0f / En);
        bmean = mean;
        brs = rsqrtf(a2 * (1.0f / En) - mean * mean + 1e-5f);
    }
    __syncthreads();
    float mean = bmean, rs = brs;
    float4 gg = ((const float4*)g)[t];
    float4 bb = ((const float4*)bta)[t];
    float4 o;
    o.x = (vv.x - mean) * rs * gg.x + bb.x;
    o.y = (vv.y - mean) * rs * gg.y + bb.y;
    o.z = (vv.z - mean) * rs * gg.z + bb.z;
    o.w = (vv.w - mean) * rs * gg.w + bb.w;
    ((float4*)(out + (size_t)row * En))[t] = o;
    if (outr)
        ((float4*)(outr + (size_t)row * En))[t] =
            make_float4(rnd32(o.x), rnd32(o.y), rnd32(o.z), rnd32(o.w));
}

// ---------------- loss (two-pass: max, then exp-sum) ----------------
__global__ void k_rowloss(const float* __restrict__ logits, const void* __restrict__ tgt,
                          float* __restrict__ rl) {
    int row = blockIdx.x, t = threadIdx.x;
    const float* lp = logits + (size_t)row * Vn;
    __shared__ float red[8];
    __shared__ float brmax;
    int w = t >> 5, lane = t & 31;
    float m = NEG_HUGE;
    for (int c = 4 * t; c < Vn; c += 1024) {
        float4 vv = *(const float4*)(lp + c);
        m = fmaxf(m, fmaxf(fmaxf(vv.x, vv.y), fmaxf(vv.z, vv.w)));
    }
#pragma unroll
    for (int off = 16; off; off >>= 1) m = fmaxf(m, __shfl_down_sync(0xffffffffu, m, off));
    if (lane == 0) red[w] = m;
    __syncthreads();
    if (t == 0) {
        float a = red[0];
#pragma unroll
        for (int i2 = 1; i2 < 8; i2++) a = fmaxf(a, red[i2]);
        brmax = a;
    }
    __syncthreads();
    float rm = brmax;
    float s = 0.f;
    for (int c = 4 * t; c < Vn; c += 1024) {
        float4 vv = *(const float4*)(lp + c);
        s += __expf(vv.x - rm) + __expf(vv.y - rm) + __expf(vv.z - rm) + __expf(vv.w - rm);
    }
#pragma unroll
    for (int off = 16; off; off >>= 1) s += __shfl_down_sync(0xffffffffu, s, off);
    if (lane == 0) red[w] = s;
    __syncthreads();
    if (t == 0) {
        float a = 0.f;
#pragma unroll
        for (int i2 = 0; i2 < 8; i2++) a += red[i2];
        bool is64 = tok_is64(tgt);
        int tv = tok_at(tgt, row, is64);
        rl[row] = (rm + logf(a)) - lp[tv];
    }
}
__global__ void k_lossfinal(const float* __restrict__ rl, float* __restrict__ dst) {
    int t = threadIdx.x;
    float s = 0.f;
    for (int i = t; i < Rn; i += 256) s += rl[i];
#pragma unroll
    for (int off = 16; off; off >>= 1) s += __shfl_down_sync(0xffffffffu, s, off);
    __shared__ float red[8];
    int w = t >> 5, lane = t & 31;
    if (lane == 0) red[w] = s;
    __syncthreads();
    if (t == 0) {
        float a = 0.f;
#pragma unroll
        for (int i2 = 0; i2 < 8; i2++) a += red[i2];
        dst[0] = a * (1.0f / Rn);
    }
}

extern "C" void kernel_launch(void* const* d_in, const int* in_sizes, int n_in,
                              void* d_out, int out_size) {
    const void* idx = d_in[0];
    const void* tgt = d_in[1];
    const float* tok = (const float*)d_in[2];
    const float* pos = (const float*)d_in[3];
    const float* Wq = (const float*)d_in[4];
    const float* Wk = (const float*)d_in[5];
    const float* Wv = (const float*)d_in[6];
    const float* Wo = (const float*)d_in[7];
    const float* bo = (const float*)d_in[8];
    const float* ln1g = (const float*)d_in[9];
    const float* ln1b = (const float*)d_in[10];
    const float* W1 = (const float*)d_in[11];
    const float* b1 = (const float*)d_in[12];
    const float* W2 = (const float*)d_in[13];
    const float* b2 = (const float*)d_in[14];
    const float* ln2g = (const float*)d_in[15];
    const float* ln2b = (const float*)d_in[16];
    const float* lnfg = (const float*)d_in[17];
    const float* lnfb = (const float*)d_in[18];
    const float* lmw = (const float*)d_in[19];
    const float* lmb = (const float*)d_in[20];
    float* out = (float*)d_out;

    float *x, *xr, *tmp, *q, *k, *v, *att, *h, *rl;
    float *wor, *w1r, *w2r, *lmwr;
    cudaGetSymbolAddress((void**)&x, g_x);
    cudaGetSymbolAddress((void**)&xr, g_xr);
    cudaGetSymbolAddress((void**)&tmp, g_tmp);
    cudaGetSymbolAddress((void**)&q, g_q);
    cudaGetSymbolAddress((void**)&k, g_k);
    cudaGetSymbolAddress((void**)&v, g_v);
    cudaGetSymbolAddress((void**)&att, g_att);
    cudaGetSymbolAddress((void**)&h, g_h);
    cudaGetSymbolAddress((void**)&rl, g_rl);
    cudaGetSymbolAddress((void**)&wor, g_wor);
    cudaGetSymbolAddress((void**)&w1r, g_w1r);
    cudaGetSymbolAddress((void**)&w2r, g_w2r);
    cudaGetSymbolAddress((void**)&lmwr, g_lmwr);

    cudaFuncSetAttribute(k_attn_tc, cudaFuncAttributeMaxDynamicSharedMemorySize, ATT_SMEM);
    const int f32_smem = 2 * FBUFB;
    cudaFuncSetAttribute(k_gemm32<0, 0>, cudaFuncAttributeMaxDynamicSharedMemorySize, f32_smem);
    cudaFuncSetAttribute(k_gemm32<1, 1>, cudaFuncAttributeMaxDynamicSharedMemorySize, f32_smem);

    // pre-round all weights to the tf32 grid (RNA), once per launch
    k_round<<<(Ln * En * En / 4 + 255) / 256, 256>>>(Wo, wor, Ln * En * En / 4);
    k_round<<<((size_t)Ln * FFn * En / 4 + 255) / 256, 256>>>(W1, w1r, Ln * FFn * En / 4);
    k_round<<<((size_t)Ln * En * FFn / 4 + 255) / 256, 256>>>(W2, w2r, Ln * En * FFn / 4);
    k_round<<<((size_t)Vn * En / 4 + 255) / 256, 256>>>(lmw, lmwr, Vn * En / 4);

    k_embed<<<Rn, 256>>>(idx, tok, pos, x);
    for (int l = 0; l < Ln; l++) {
        k_qkv<<<Rn / 64, 256>>>(x, Wq + (size_t)l * Dh * Dh, Wk + (size_t)l * Dh * Dh,
                                Wv + (size_t)l * Dh * Dh, q, k, v);
        k_attn_tc<<<dim3(Tn / 128, Hn, Bn), 256, ATT_SMEM>>>(q, k, v, att);
        k_gemm32<0, 0><<<dim3(Rn / 128, En / 128), 256, f32_smem>>>(
            att, wor + (size_t)l * En * En, bo + (size_t)l * En, tmp, Rn, En, En);
        k_addln<<<Rn, 256>>>(tmp, x, ln1g + (size_t)l * En, ln1b + (size_t)l * En, x, xr, 1);
        k_gemm32<1, 1><<<dim3(Rn / 128, FFn / 128), 256, f32_smem>>>(
            xr, w1r + (size_t)l * FFn * En, b1 + (size_t)l * FFn, h, Rn, FFn, En);
        k_gemm32<0, 0><<<dim3(Rn / 128, En / 128), 256, f32_smem>>>(
            h, w2r + (size_t)l * En * FFn, b2 + (size_t)l * En, tmp, Rn, En, FFn);
        k_addln<<<Rn, 256>>>(tmp, x, ln2g + (size_t)l * En, ln2b + (size_t)l * En, x, nullptr, 1);
    }
    k_addln<<<Rn, 256>>>(x, x, lnfg, lnfb, x, xr, 0);
    k_gemm32<0, 0><<<dim3(Rn / 128, Vn / 128), 256, f32_smem>>>(xr, lmwr, lmb, out, Rn, Vn, En);
    if ((long long)out_size > (long long)Rn * Vn) {
        k_rowloss<<<Rn, 256>>>(out, tgt, rl);
        k_lossfinal<<<1, 256>>>(rl, out + (size_t)Rn * Vn);
    }
}

// round 17
// speedup vs baseline: 1.2071x; 1.0072x over previous
#include <cuda_runtime.h>
#include <cuda_bf16.h>
#include <math.h>
#include <stdint.h>

#define Bn 4
#define Tn 2048
#define En 1024
#define Hn 16
#define Dh 64
#define Ln 4
#define FFn 4096
#define Vn 32000
#define Rn 8192
#define NEG_HUGE (-1e30f)

__device__ float g_x[Rn * En];
__device__ float g_xr[Rn * En];
__device__ float g_tmp[Rn * En];
__device__ float g_q[Rn * En];
__device__ float g_k[Rn * En];
__device__ float g_v[Rn * En];
__device__ float g_att[Rn * En];
__device__ float g_h[(size_t)Rn * FFn];
__device__ float g_wor[(size_t)Ln * En * En];
__device__ float g_w1r[(size_t)Ln * FFn * En];
__device__ float g_w2r[(size_t)Ln * En * FFn];
__device__ float g_lmwr[(size_t)Vn * En];
__device__ float g_rl[Rn];

// ---------------- helpers ----------------
__device__ __forceinline__ uint32_t smem_u32(const void* p) {
    uint32_t a;
    asm("{ .reg .u64 t; cvta.to.shared.u64 t, %1; cvt.u32.u64 %0, t; }" : "=r"(a) : "l"(p));
    return a;
}
__device__ __forceinline__ void mma_tf32(float* c, const uint32_t* a, const uint32_t* b) {
    asm volatile("mma.sync.aligned.m16n8k8.row.col.f32.tf32.tf32.f32 "
                 "{%0,%1,%2,%3}, {%4,%5,%6,%7}, {%8,%9}, {%0,%1,%2,%3};"
                 : "+f"(c[0]), "+f"(c[1]), "+f"(c[2]), "+f"(c[3])
                 : "r"(a[0]), "r"(a[1]), "r"(a[2]), "r"(a[3]), "r"(b[0]), "r"(b[1]));
}
__device__ __forceinline__ uint32_t to_tf32(float f) {
    uint32_t r;
    asm("cvt.rna.tf32.f32 %0, %1;" : "=r"(r) : "f"(f));
    return r;
}
__device__ __forceinline__ float rnd32(float f) { return __uint_as_float(to_tf32(f)); }
__device__ __forceinline__ uint32_t frg(float f) { return __float_as_uint(f); }
#define CP16(dst, src) asm volatile("cp.async.cg.shared.global [%0], [%1], 16;" \
    :: "r"(dst), "l"(__cvta_generic_to_global(src)) : "memory")
#define CPCOMMIT() asm volatile("cp.async.commit_group;" ::: "memory")
#define CPWAIT1() asm volatile("cp.async.wait_group 1;" ::: "memory")
#define CPWAIT0() asm volatile("cp.async.wait_group 0;" ::: "memory")

__device__ __forceinline__ bool tok_is64(const void* p) {
    const unsigned long long* q = (const unsigned long long*)p;
    unsigned long long acc = 0ull;
#pragma unroll
    for (int i = 0; i < 8; i++) acc |= (q[i] & 0xFFFFFFFF00000000ull);
    return acc == 0ull;
}
__device__ __forceinline__ int tok_at(const void* p, int i, bool is64) {
    return is64 ? (int)((const long long*)p)[i] : ((const int*)p)[i];
}

// ---------------- weight pre-round (fp32 -> tf32 grid) ----------------
__global__ void k_round(const float* __restrict__ s, float* __restrict__ d, int n4) {
    int i = blockIdx.x * 256 + threadIdx.x;
    if (i >= n4) return;
    float4 v = ((const float4*)s)[i];
    ((float4*)d)[i] = make_float4(rnd32(v.x), rnd32(v.y), rnd32(v.z), rnd32(v.w));
}

// ---------------- embedding ----------------
__global__ void k_embed(const void* __restrict__ idx, const float* __restrict__ tok,
                        const float* __restrict__ pos, float* __restrict__ x) {
    int row = blockIdx.x, t = threadIdx.x;
    bool is64 = tok_is64(idx);
    int token = tok_at(idx, row, is64);
    int tt = row & (Tn - 1);
    float4 a = ((const float4*)(tok + (size_t)token * En))[t];
    float4 p = ((const float4*)(pos + (size_t)tt * En))[t];
    ((float4*)(x + (size_t)row * En))[t] = make_float4(a.x + p.x, a.y + p.y, a.z + p.z, a.w + p.w);
}

// ---------------- QKV (fp32) ----------------
__global__ void __launch_bounds__(256) k_qkv(
    const float* __restrict__ x, const float* __restrict__ Wq,
    const float* __restrict__ Wk, const float* __restrict__ Wv,
    float* __restrict__ q, float* __restrict__ k, float* __restrict__ v) {
    __shared__ float xs[64 * 68];
    __shared__ float wt[64 * 68];
    int r0 = blockIdx.x * 64;
    int b = r0 >> 11, t0 = r0 & 2047;
    int tid = threadIdx.x, tx = tid & 15, ty = tid >> 4;
    for (int h = 0; h < Hn; h++) {
        __syncthreads();
        for (int n = tid; n < 64 * 16; n += 256) {
            int row = n >> 4, c4 = n & 15;
            *(float4*)&xs[row * 68 + c4 * 4] =
                *(const float4*)(x + (size_t)(r0 + row) * En + h * 64 + c4 * 4);
        }
        for (int mm = 0; mm < 3; mm++) {
            const float* Wm = (mm == 0) ? Wq : (mm == 1) ? Wk : Wv;
            float* Om = (mm == 0) ? q : (mm == 1) ? k : v;
            __syncthreads();
            for (int n = tid; n < 64 * 16; n += 256) {
                int e = n >> 4, c4 = n & 15;
                float4 val = *(const float4*)(Wm + e * 64 + c4 * 4);
                wt[(c4 * 4 + 0) * 68 + e] = val.x;
                wt[(c4 * 4 + 1) * 68 + e] = val.y;
                wt[(c4 * 4 + 2) * 68 + e] = val.z;
                wt[(c4 * 4 + 3) * 68 + e] = val.w;
            }
            __syncthreads();
            float acc[4][4] = {};
            for (int d = 0; d < 64; d++) {
                float a0 = xs[(ty * 4 + 0) * 68 + d];
                float a1 = xs[(ty * 4 + 1) * 68 + d];
                float a2 = xs[(ty * 4 + 2) * 68 + d];
                float a3 = xs[(ty * 4 + 3) * 68 + d];
                float4 bv = *(const float4*)&wt[d * 68 + tx * 4];
                acc[0][0] += a0 * bv.x; acc[0][1] += a0 * bv.y; acc[0][2] += a0 * bv.z; acc[0][3] += a0 * bv.w;
                acc[1][0] += a1 * bv.x; acc[1][1] += a1 * bv.y; acc[1][2] += a1 * bv.z; acc[1][3] += a1 * bv.w;
                acc[2][0] += a2 * bv.x; acc[2][1] += a2 * bv.y; acc[2][2] += a2 * bv.z; acc[2][3] += a2 * bv.w;
                acc[3][0] += a3 * bv.x; acc[3][1] += a3 * bv.y; acc[3][2] += a3 * bv.z; acc[3][3] += a3 * bv.w;
            }
#pragma unroll
            for (int ri = 0; ri < 4; ri++) {
                size_t off = ((size_t)((b * Hn + h) * Tn + t0 + ty * 4 + ri)) * Dh + tx * 4;
                *(float4*)(Om + off) = make_float4(acc[ri][0], acc[ri][1], acc[ri][2], acc[ri][3]);
            }
        }
    }
}

// ---------------- tensor-core flash attention: shfl P-transpose, 2 blocks/SM --------
#define ASTR 68
#define KOFF (128 * ASTR * 4)
#define VOFF (KOFF + 2 * 17408)
#define ATT_SMEM (VOFF + 2 * 17408)
__global__ void __launch_bounds__(256, 2) k_attn_tc(
    const float* __restrict__ q, const float* __restrict__ k,
    const float* __restrict__ v, float* __restrict__ o) {
    extern __shared__ float sm[];
    uint32_t sb = smem_u32(sm);
    int qt = blockIdx.x, hh = blockIdx.y, b = blockIdx.z;
    int tid = threadIdx.x, w = tid >> 5, l = tid & 31;
    int lg = l >> 2, lt = l & 3;

    const float* qb = q + ((size_t)(b * Hn + hh) * Tn + qt * 128) * Dh;
    const float* kb = k + ((size_t)(b * Hn + hh) * Tn) * Dh;
    const float* vb = v + ((size_t)(b * Hn + hh) * Tn) * Dh;

    {
        int r = tid >> 1, c = (tid & 1) * 32;
#pragma unroll
        for (int i = 0; i < 8; i++)
            *(float4*)&sm[r * ASTR + c + i * 4] = *(const float4*)(qb + r * 64 + c + i * 4);
    }
#define FILLKV(st, kt) do {                                                    \
    int _r = tid >> 2, _c = (tid & 3) * 16;                                    \
    const float* _kp = kb + ((size_t)(kt) * 64 + _r) * 64 + _c;                \
    const float* _vp = vb + ((size_t)(kt) * 64 + _r) * 64 + _c;                \
    uint32_t _dk = sb + KOFF + (st) * 17408 + (uint32_t)(_r * ASTR + _c) * 4;  \
    uint32_t _dv = sb + VOFF + (st) * 17408 + (uint32_t)(_r * ASTR + _c) * 4;  \
    _Pragma("unroll")                                                          \
    for (int _i = 0; _i < 4; _i++) {                                           \
        CP16(_dk + _i * 16, _kp + _i * 4);                                     \
        CP16(_dv + _i * 16, _vp + _i * 4);                                     \
    }                                                                          \
} while (0)

    FILLKV(0, 0);
    CPCOMMIT();
    __syncthreads();

    uint32_t qf[8][4];
#pragma unroll
    for (int ks = 0; ks < 8; ks++) {
        const float* qp = &sm[(w * 16 + lg) * ASTR + ks * 8 + lt];
        qf[ks][0] = frg(qp[0]);
        qf[ks][1] = frg(qp[8 * ASTR]);
        qf[ks][2] = frg(qp[4]);
        qf[ks][3] = frg(qp[8 * ASTR + 4]);
    }

    float m0 = NEG_HUGE, m1 = NEG_HUGE, l0 = 0.f, l1 = 0.f;
    float oacc[8][4];
#pragma unroll
    for (int nt = 0; nt < 8; nt++)
#pragma unroll
        for (int c = 0; c < 4; c++) oacc[nt][c] = 0.f;

    int gr0 = qt * 128 + w * 16 + lg;
    int gr1 = gr0 + 8;
    int src0 = (l & ~3) + (lt >> 1);
    int src1 = src0 + 2;
    bool oddl = (lt & 1);

    int nkt = 2 * qt + 1;
    for (int kt = 0; kt <= nkt; kt++) {
        __syncthreads();
        if (kt + 1 <= nkt) {
            FILLKV((kt + 1) & 1, kt + 1);
            CPCOMMIT();
            CPWAIT1();
        } else {
            CPWAIT0();
        }
        __syncthreads();
        const float* Ks = sm + KOFF / 4 + (kt & 1) * 4352;
        const float* Vs = sm + VOFF / 4 + (kt & 1) * 4352;

        float sacc[8][4];
#pragma unroll
        for (int nt = 0; nt < 8; nt++)
#pragma unroll
            for (int c = 0; c < 4; c++) sacc[nt][c] = 0.f;
#pragma unroll
        for (int ks = 0; ks < 8; ks++) {
#pragma unroll
            for (int nt = 0; nt < 8; nt++) {
                uint32_t bf[2];
                const float* kp = &Ks[(nt * 8 + lg) * ASTR + ks * 8 + lt];
                bf[0] = frg(kp[0]);
                bf[1] = frg(kp[4]);
                mma_tf32(sacc[nt], qf[ks], bf);
            }
        }
        float mx0 = NEG_HUGE, mx1 = NEG_HUGE;
#pragma unroll
        for (int nt = 0; nt < 8; nt++) {
#pragma unroll
            for (int j = 0; j < 2; j++) {
                int gc = kt * 64 + nt * 8 + lt * 2 + j;
                float s0 = sacc[nt][j] * 0.125f;
                float s1 = sacc[nt][2 + j] * 0.125f;
                if (gc > gr0) s0 = NEG_HUGE;
                if (gc > gr1) s1 = NEG_HUGE;
                sacc[nt][j] = s0;
                sacc[nt][2 + j] = s1;
                mx0 = fmaxf(mx0, s0);
                mx1 = fmaxf(mx1, s1);
            }
        }
        mx0 = fmaxf(mx0, __shfl_xor_sync(0xffffffffu, mx0, 1));
        mx0 = fmaxf(mx0, __shfl_xor_sync(0xffffffffu, mx0, 2));
        mx1 = fmaxf(mx1, __shfl_xor_sync(0xffffffffu, mx1, 1));
        mx1 = fmaxf(mx1, __shfl_xor_sync(0xffffffffu, mx1, 2));
        float mn0 = fmaxf(m0, mx0), mn1 = fmaxf(m1, mx1);
        float cr0 = __expf(m0 - mn0), cr1 = __expf(m1 - mn1);
        m0 = mn0; m1 = mn1;
        float ps0 = 0.f, ps1 = 0.f;
#pragma unroll
        for (int nt = 0; nt < 8; nt++) {
#pragma unroll
            for (int j = 0; j < 2; j++) {
                float p0 = __expf(sacc[nt][j] - mn0);
                float p1 = __expf(sacc[nt][2 + j] - mn1);
                sacc[nt][j] = p0;
                sacc[nt][2 + j] = p1;
                ps0 += p0;
                ps1 += p1;
            }
        }
        ps0 += __shfl_xor_sync(0xffffffffu, ps0, 1);
        ps0 += __shfl_xor_sync(0xffffffffu, ps0, 2);
        ps1 += __shfl_xor_sync(0xffffffffu, ps1, 1);
        ps1 += __shfl_xor_sync(0xffffffffu, ps1, 2);
        l0 = l0 * cr0 + ps0;
        l1 = l1 * cr1 + ps1;
#pragma unroll
        for (int nt = 0; nt < 8; nt++) {
            oacc[nt][0] *= cr0; oacc[nt][1] *= cr0;
            oacc[nt][2] *= cr1; oacc[nt][3] *= cr1;
        }
        // ---- PV: A-fragments from sacc via 4-lane shfl transpose ----
#pragma unroll
        for (int s = 0; s < 8; s++) {
            float v00 = __shfl_sync(0xffffffffu, sacc[s][0], src0);
            float v01 = __shfl_sync(0xffffffffu, sacc[s][1], src0);
            float v10 = __shfl_sync(0xffffffffu, sacc[s][2], src0);
            float v11 = __shfl_sync(0xffffffffu, sacc[s][3], src0);
            float w00 = __shfl_sync(0xffffffffu, sacc[s][0], src1);
            float w01 = __shfl_sync(0xffffffffu, sacc[s][1], src1);
            float w10 = __shfl_sync(0xffffffffu, sacc[s][2], src1);
            float w11 = __shfl_sync(0xffffffffu, sacc[s][3], src1);
            uint32_t af[4];
            af[0] = frg(oddl ? v01 : v00);
            af[1] = frg(oddl ? v11 : v10);
            af[2] = frg(oddl ? w01 : w00);
            af[3] = frg(oddl ? w11 : w10);
#pragma unroll
            for (int nt = 0; nt < 8; nt++) {
                uint32_t bf[2];
                const float* vp = &Vs[(s * 8 + lt) * ASTR + nt * 8 + lg];
                bf[0] = frg(vp[0]);
                bf[1] = frg(vp[4 * ASTR]);
                mma_tf32(oacc[nt], af, bf);
            }
        }
    }
    // epilogue: normalize + RNA-round to tf32 grid (att feeds Wo GEMM via frg)
    float inv0 = 1.f / l0, inv1 = 1.f / l1;
    size_t base0 = ((size_t)(b * Tn) + gr0) * En + hh * 64;
    size_t base1 = base0 + (size_t)8 * En;
#pragma unroll
    for (int nt = 0; nt < 8; nt++) {
        int cc = nt * 8 + lt * 2;
        *(float2*)(o + base0 + cc) = make_float2(rnd32(oacc[nt][0] * inv0), rnd32(oacc[nt][1] * inv0));
        *(float2*)(o + base1 + cc) = make_float2(rnd32(oacc[nt][2] * inv1), rnd32(oacc[nt][3] * inv1));
    }
}

// ---------------- tf32 single-pass GEMM (pre-rounded inputs, raw-bit operands) ------
#define FSTR 36
#define FMATB (128 * FSTR * 4)
#define FBUFB (2 * FMATB)
template <int ACT, int ROUND>
__global__ void __launch_bounds__(256, 2) k_gemm32(
    const float* __restrict__ X, const float* __restrict__ W,
    const float* __restrict__ bias, float* __restrict__ Y, int M, int N, int K) {
    extern __shared__ char dsm[];
    uint32_t sb = smem_u32(dsm);
    int tid = threadIdx.x, wid = tid >> 5, lane = tid & 31;
    int bm = blockIdx.x * 128, bn = blockIdx.y * 128;
    int wm = (wid >> 2) * 64, wn = (wid & 3) * 32;
    float acc[4][4][4];
#pragma unroll
    for (int a = 0; a < 4; a++)
#pragma unroll
        for (int b = 0; b < 4; b++)
#pragma unroll
            for (int c = 0; c < 4; c++) acc[a][b][c] = 0.f;
    int NK = K >> 5;
#define F32FILL(bsel, kc) do {                                                \
    uint32_t _b = sb + (bsel) * FBUFB;                                        \
    int _k0 = (kc) * 32;                                                      \
    _Pragma("unroll")                                                         \
    for (int it = 0; it < 4; it++) {                                          \
        int _i = tid + it * 256;                                              \
        int _r = _i >> 3, _c = (_i & 7) * 4;                                  \
        CP16(_b + (uint32_t)(_r * FSTR + _c) * 4, X + (size_t)(bm + _r) * K + _k0 + _c); \
        CP16(_b + FMATB + (uint32_t)(_r * FSTR + _c) * 4, W + (size_t)(bn + _r) * K + _k0 + _c); \
    }                                                                         \
} while (0)
    F32FILL(0, 0);
    CPCOMMIT();
    for (int kc = 0; kc < NK; kc++) {
        CPWAIT0();
        __syncthreads();
        if (kc + 1 < NK) {
            F32FILL((kc + 1) & 1, kc + 1);
            CPCOMMIT();
        }
        const float* fA = (const float*)(dsm + (kc & 1) * FBUFB);
        const float* fB = (const float*)(dsm + (kc & 1) * FBUFB + FMATB);
#pragma unroll
        for (int ks = 0; ks < 4; ks++) {
            uint32_t a[4][4], b[4][2];
#pragma unroll
            for (int mt = 0; mt < 4; mt++) {
                const float* pa = fA + (wm + mt * 16 + (lane >> 2)) * FSTR + ks * 8 + (lane & 3);
                a[mt][0] = frg(pa[0]);
                a[mt][1] = frg(pa[8 * FSTR]);
                a[mt][2] = frg(pa[4]);
                a[mt][3] = frg(pa[8 * FSTR + 4]);
            }
#pragma unroll
            for (int nt = 0; nt < 4; nt++) {
                const float* pb = fB + (wn + nt * 8 + (lane >> 2)) * FSTR + ks * 8 + (lane & 3);
                b[nt][0] = frg(pb[0]);
                b[nt][1] = frg(pb[4]);
            }
#pragma unroll
            for (int mt = 0; mt < 4; mt++)
#pragma unroll
                for (int nt = 0; nt < 4; nt++) mma_tf32(acc[mt][nt], a[mt], b[nt]);
        }
    }
#pragma unroll
    for (int mt = 0; mt < 4; mt++) {
#pragma unroll
        for (int nt = 0; nt < 4; nt++) {
            int rr = bm + wm + mt * 16 + (lane >> 2);
            int cc = bn + wn + nt * 8 + (lane & 3) * 2;
            float b0 = __ldg(bias + cc), b1 = __ldg(bias + cc + 1);
            float v0 = acc[mt][nt][0] + b0, v1 = acc[mt][nt][1] + b1;
            float v2 = acc[mt][nt][2] + b0, v3 = acc[mt][nt][3] + b1;
            if (ACT) {
                v0 = 0.5f * v0 * (1.0f + erff(v0 * 0.70710678f));
                v1 = 0.5f * v1 * (1.0f + erff(v1 * 0.70710678f));
                v2 = 0.5f * v2 * (1.0f + erff(v2 * 0.70710678f));
                v3 = 0.5f * v3 * (1.0f + erff(v3 * 0.70710678f));
            }
            if (ROUND) {
                v0 = rnd32(v0); v1 = rnd32(v1); v2 = rnd32(v2); v3 = rnd32(v3);
            }
            *(float2*)(Y + (size_t)rr * N + cc) = make_float2(v0, v1);
            *(float2*)(Y + (size_t)(rr + 8) * N + cc) = make_float2(v2, v3);
        }
    }
}

// ---------------- residual add + layernorm; optional rounded copy -------------------
__global__ void k_addln(const float* __restrict__ a, const float* __restrict__ res,
                        const float* __restrict__ g, const float* __restrict__ bta,
                        float* __restrict__ out, float* __restrict__ outr, int hasres) {
    int row = blockIdx.x, t = threadIdx.x;
    float4 vv = ((const float4*)(a + (size_t)row * En))[t];
    if (hasres) {
        float4 r = ((const float4*)(res + (size_t)row * En))[t];
        vv.x += r.x; vv.y += r.y; vv.z += r.z; vv.w += r.w;
    }
    float s1 = vv.x + vv.y + vv.z + vv.w;
    float s2 = vv.x * vv.x + vv.y * vv.y + vv.z * vv.z + vv.w * vv.w;
#pragma unroll
    for (int off = 16; off; off >>= 1) {
        s1 += __shfl_down_sync(0xffffffffu, s1, off);
        s2 += __shfl_down_sync(0xffffffffu, s2, off);
    }
    __shared__ float r1[8], r2[8];
    __shared__ float bmean, brs;
    int w = t >> 5, lane = t & 31;
    if (lane == 0) { r1[w] = s1; r2[w] = s2; }
    __syncthreads();
    if (t == 0) {
        float a1 = 0.f, a2 = 0.f;
#pragma unroll
        for (int i2 = 0; i2 < 8; i2++) { a1 += r1[i2]; a2 += r2[i2]; }
        float mean = a1 * (1.0f / En);
        bmean = mean;
        brs = rsqrtf(a2 * (1.0f / En) - mean * mean + 1e-5f);
    }
    __syncthreads();
    float mean = bmean, rs = brs;
    float4 gg = ((const float4*)g)[t];
    float4 bb = ((const float4*)bta)[t];
    float4 o;
    o.x = (vv.x - mean) * rs * gg.x + bb.x;
    o.y = (vv.y - mean) * rs * gg.y + bb.y;
    o.z = (vv.z - mean) * rs * gg.z + bb.z;
    o.w = (vv.w - mean) * rs * gg.w + bb.w;
    ((float4*)(out + (size_t)row * En))[t] = o;
    if (outr)
        ((float4*)(outr + (size_t)row * En))[t] =
            make_float4(rnd32(o.x), rnd32(o.y), rnd32(o.z), rnd32(o.w));
}

// ---------------- loss (two-pass: max, then exp-sum) ----------------
__global__ void k_rowloss(const float* __restrict__ logits, const void* __restrict__ tgt,
                          float* __restrict__ rl) {
    int row = blockIdx.x, t = threadIdx.x;
    const float* lp = logits + (size_t)row * Vn;
    __shared__ float red[8];
    __shared__ float brmax;
    int w = t >> 5, lane = t & 31;
    float m = NEG_HUGE;
    for (int c = 4 * t; c < Vn; c += 1024) {
        float4 vv = *(const float4*)(lp + c);
        m = fmaxf(m, fmaxf(fmaxf(vv.x, vv.y), fmaxf(vv.z, vv.w)));
    }
#pragma unroll
    for (int off = 16; off; off >>= 1) m = fmaxf(m, __shfl_down_sync(0xffffffffu, m, off));
    if (lane == 0) red[w] = m;
    __syncthreads();
    if (t == 0) {
        float a = red[0];
#pragma unroll
        for (int i2 = 1; i2 < 8; i2++) a = fmaxf(a, red[i2]);
        brmax = a;
    }
    __syncthreads();
    float rm = brmax;
    float s = 0.f;
    for (int c = 4 * t; c < Vn; c += 1024) {
        float4 vv = *(const float4*)(lp + c);
        s += __expf(vv.x - rm) + __expf(vv.y - rm) + __expf(vv.z - rm) + __expf(vv.w - rm);
    }
#pragma unroll
    for (int off = 16; off; off >>= 1) s += __shfl_down_sync(0xffffffffu, s, off);
    if (lane == 0) red[w] = s;
    __syncthreads();
    if (t == 0) {
        float a = 0.f;
#pragma unroll
        for (int i2 = 0; i2 < 8; i2++) a += red[i2];
        bool is64 = tok_is64(tgt);
        int tv = tok_at(tgt, row, is64);
        rl[row] = (rm + logf(a)) - lp[tv];
    }
}
__global__ void k_lossfinal(const float* __restrict__ rl, float* __restrict__ dst) {
    int t = threadIdx.x;
    float s = 0.f;
    for (int i = t; i < Rn; i += 256) s += rl[i];
#pragma unroll
    for (int off = 16; off; off >>= 1) s += __shfl_down_sync(0xffffffffu, s, off);
    __shared__ float red[8];
    int w = t >> 5, lane = t & 31;
    if (lane == 0) red[w] = s;
    __syncthreads();
    if (t == 0) {
        float a = 0.f;
#pragma unroll
        for (int i2 = 0; i2 < 8; i2++) a += red[i2];
        dst[0] = a * (1.0f / Rn);
    }
}

extern "C" void kernel_launch(void* const* d_in, const int* in_sizes, int n_in,
                              void* d_out, int out_size) {
    const void* idx = d_in[0];
    const void* tgt = d_in[1];
    const float* tok = (const float*)d_in[2];
    const float* pos = (const float*)d_in[3];
    const float* Wq = (const float*)d_in[4];
    const float* Wk = (const float*)d_in[5];
    const float* Wv = (const float*)d_in[6];
    const float* Wo = (const float*)d_in[7];
    const float* bo = (const float*)d_in[8];
    const float* ln1g = (const float*)d_in[9];
    const float* ln1b = (const float*)d_in[10];
    const float* W1 = (const float*)d_in[11];
    const float* b1 = (const float*)d_in[12];
    const float* W2 = (const float*)d_in[13];
    const float* b2 = (const float*)d_in[14];
    const float* ln2g = (const float*)d_in[15];
    const float* ln2b = (const float*)d_in[16];
    const float* lnfg = (const float*)d_in[17];
    const float* lnfb = (const float*)d_in[18];
    const float* lmw = (const float*)d_in[19];
    const float* lmb = (const float*)d_in[20];
    float* out = (float*)d_out;

    float *x, *xr, *tmp, *q, *k, *v, *att, *h, *rl;
    float *wor, *w1r, *w2r, *lmwr;
    cudaGetSymbolAddress((void**)&x, g_x);
    cudaGetSymbolAddress((void**)&xr, g_xr);
    cudaGetSymbolAddress((void**)&tmp, g_tmp);
    cudaGetSymbolAddress((void**)&q, g_q);
    cudaGetSymbolAddress((void**)&k, g_k);
    cudaGetSymbolAddress((void**)&v, g_v);
    cudaGetSymbolAddress((void**)&att, g_att);
    cudaGetSymbolAddress((void**)&h, g_h);
    cudaGetSymbolAddress((void**)&rl, g_rl);
    cudaGetSymbolAddress((void**)&wor, g_wor);
    cudaGetSymbolAddress((void**)&w1r, g_w1r);
    cudaGetSymbolAddress((void**)&w2r, g_w2r);
    cudaGetSymbolAddress((void**)&lmwr, g_lmwr);

    cudaFuncSetAttribute(k_attn_tc, cudaFuncAttributeMaxDynamicSharedMemorySize, ATT_SMEM);
    const int f32_smem = 2 * FBUFB;
    cudaFuncSetAttribute(k_gemm32<0, 0>, cudaFuncAttributeMaxDynamicSharedMemorySize, f32_smem);
    cudaFuncSetAttribute(k_gemm32<1, 1>, cudaFuncAttributeMaxDynamicSharedMemorySize, f32_smem);

    k_round<<<(Ln * En * En / 4 + 255) / 256, 256>>>(Wo, wor, Ln * En * En / 4);
    k_round<<<((size_t)Ln * FFn * En / 4 + 255) / 256, 256>>>(W1, w1r, Ln * FFn * En / 4);
    k_round<<<((size_t)Ln * En * FFn / 4 + 255) / 256, 256>>>(W2, w2r, Ln * En * FFn / 4);
    k_round<<<((size_t)Vn * En / 4 + 255) / 256, 256>>>(lmw, lmwr, Vn * En / 4);

    k_embed<<<Rn, 256>>>(idx, tok, pos, x);
    for (int l = 0; l < Ln; l++) {
        k_qkv<<<Rn / 64, 256>>>(x, Wq + (size_t)l * Dh * Dh, Wk + (size_t)l * Dh * Dh,
                                Wv + (size_t)l * Dh * Dh, q, k, v);
        k_attn_tc<<<dim3(Tn / 128, Hn, Bn), 256, ATT_SMEM>>>(q, k, v, att);
        k_gemm32<0, 0><<<dim3(Rn / 128, En / 128), 256, f32_smem>>>(
            att, wor + (size_t)l * En * En, bo + (size_t)l * En, tmp, Rn, En, En);
        k_addln<<<Rn, 256>>>(tmp, x, ln1g + (size_t)l * En, ln1b + (size_t)l * En, x, xr, 1);
        k_gemm32<1, 1><<<dim3(Rn / 128, FFn / 128), 256, f32_smem>>>(
            xr, w1r + (size_t)l * FFn * En, b1 + (size_t)l * FFn, h, Rn, FFn, En);
        k_gemm32<0, 0><<<dim3(Rn / 128, En / 128), 256, f32_smem>>>(
            h, w2r + (size_t)l * En * FFn, b2 + (size_t)l * En, tmp, Rn, En, FFn);
        k_addln<<<Rn, 256>>>(tmp, x, ln2g + (size_t)l * En, ln2b + (size_t)l * En, x, nullptr, 1);
    }
    k_addln<<<Rn, 256>>>(x, x, lnfg, lnfb, x, xr, 0);
    k_gemm32<0, 0><<<dim3(Rn / 128, Vn / 128), 256, f32_smem>>>(xr, lmwr, lmb, out, Rn, Vn, En);
    if ((long long)out_size > (long long)Rn * Vn) {
        k_rowloss<<<Rn, 256>>>(out, tgt, rl);
        k_lossfinal<<<1, 256>>>(rl, out + (size_t)Rn * Vn);
    }
}